// round 7
// baseline (speedup 1.0000x reference)
#include <cuda_runtime.h>
#include <cuda_bf16.h>
#include <cstdint>

#define NN 50000
#define DD 256
#define EE 320000
#define TOT (NN * DD)
#define MTILE 128
#define NBLKY ((NN + MTILE - 1) / MTILE)   // 391

typedef unsigned short ushortT;

// ---------------- scratch (static __device__ — no allocation allowed) ----------------
__device__ int g_cnt_a[NN], g_cnt_b[NN], g_cur_a[NN], g_cur_b[NN];
__device__ int g_off_a[NN + 1], g_off_b[NN + 1];
__device__ int g_csr_a[EE], g_csr_b[EE];
__device__ int g_blk[2][49], g_blkoff[2][49];
// packed u32 (hi|lo<<16) activations for segmean gathers
__device__ unsigned g_pxs[TOT], g_pxt[TOT], g_pxt0[TOT];
// bf16 hi/lo planes for gemm A inputs / out_kernel
__device__ ushortT g_hxs[TOT], g_lxs[TOT], g_hxt[TOT], g_lxt[TOT];
__device__ ushortT g_hma[TOT], g_lma[TOT], g_hmb[TOT], g_lmb[TOT];
__device__ ushortT g_hxs0[TOT], g_lxs0[TOT], g_hxs1[TOT], g_lxs1[TOT];
// pre-transposed bf16 hi/lo weights: 8 matrices of [n=256][k=256]
__device__ __nv_bfloat16 g_wbh[8 * 65536], g_wbl[8 * 65536];

// ---------------- threefry-2x32 (exactly JAX's) ----------------
__host__ __device__ __forceinline__ unsigned rotl32(unsigned x, int d) {
    return (x << d) | (x >> (32 - d));
}

__host__ __device__ __forceinline__ void tf2x32(unsigned k0, unsigned k1,
                                                unsigned x0, unsigned x1,
                                                unsigned& o0, unsigned& o1) {
    unsigned ks2 = k0 ^ k1 ^ 0x1BD11BDAu;
    x0 += k0; x1 += k1;
#define TF_ROUND(r) { x0 += x1; x1 = rotl32(x1, r); x1 ^= x0; }
    TF_ROUND(13) TF_ROUND(15) TF_ROUND(26) TF_ROUND(6)
    x0 += k1;  x1 += ks2 + 1u;
    TF_ROUND(17) TF_ROUND(29) TF_ROUND(16) TF_ROUND(24)
    x0 += ks2; x1 += k0 + 2u;
    TF_ROUND(13) TF_ROUND(15) TF_ROUND(26) TF_ROUND(6)
    x0 += k0;  x1 += k1 + 3u;
    TF_ROUND(17) TF_ROUND(29) TF_ROUND(16) TF_ROUND(24)
    x0 += k1;  x1 += ks2 + 4u;
    TF_ROUND(13) TF_ROUND(15) TF_ROUND(26) TF_ROUND(6)
    x0 += ks2; x1 += k0 + 5u;
#undef TF_ROUND
    o0 = x0; o1 = x1;
}

__device__ __forceinline__ unsigned jax_bits32(unsigned k0, unsigned k1, unsigned i) {
    unsigned o0, o1;
    tf2x32(k0, k1, 0u, i, o0, o1);
    return o0 ^ o1;
}

__device__ __forceinline__ uint32_t smem_u32(const void* p) {
    uint32_t a;
    asm("{ .reg .u64 t; cvta.to.shared.u64 t, %1; cvt.u32.u64 %0, t; }" : "=r"(a) : "l"(p));
    return a;
}

// ---------------- packed bf16-split helpers ----------------
__device__ __forceinline__ unsigned pack_split(float v) {
    __nv_bfloat16 h = __float2bfloat16(v);
    unsigned hu = (unsigned)*(unsigned short*)&h;
    float hf = __uint_as_float(hu << 16);
    __nv_bfloat16 l = __float2bfloat16(v - hf);
    unsigned lu = (unsigned)*(unsigned short*)&l;
    return hu | (lu << 16);
}

__device__ __forceinline__ float unpack_val(unsigned p) {
    return __uint_as_float(p << 16) + __uint_as_float(p & 0xFFFF0000u);
}

// ---------------- CSR build ----------------
__global__ void zero_kernel() {
    int i = blockIdx.x * blockDim.x + threadIdx.x;
    if (i < NN) { g_cnt_a[i] = 0; g_cnt_b[i] = 0; g_cur_a[i] = 0; g_cur_b[i] = 0; }
}

__global__ void count_kernel(const int* __restrict__ dst_a, const int* __restrict__ dst_b) {
    int e = blockIdx.x * blockDim.x + threadIdx.x;
    if (e < EE) {
        atomicAdd(&g_cnt_a[dst_a[e]], 1);
        atomicAdd(&g_cnt_b[dst_b[e]], 1);
    }
}

__global__ void scan_pre() {
    int y = blockIdx.y;
    const int* cnt = y ? g_cnt_b : g_cnt_a;
    int* off = y ? g_off_b : g_off_a;
    __shared__ int sb[256];
    int t = threadIdx.x;
    int base = blockIdx.x * 1024 + t * 4;
    int v[4]; int s = 0;
#pragma unroll
    for (int i = 0; i < 4; i++) {
        int idx = base + i;
        v[i] = (idx < NN) ? cnt[idx] : 0;
        s += v[i];
    }
    sb[t] = s;
    __syncthreads();
    for (int d = 1; d < 256; d <<= 1) {
        int x = (t >= d) ? sb[t - d] : 0;
        __syncthreads();
        sb[t] += x;
        __syncthreads();
    }
    int run = sb[t] - s;
#pragma unroll
    for (int i = 0; i < 4; i++) {
        int idx = base + i;
        if (idx < NN) off[idx] = run;
        run += v[i];
    }
    if (t == 255) g_blk[y][blockIdx.x] = sb[255];
}

__global__ void scan_mid() {
    int y = blockIdx.y;
    int* off = y ? g_off_b : g_off_a;
    __shared__ int sb[64];
    int t = threadIdx.x;
    int v = (t < 49) ? g_blk[y][t] : 0;
    sb[t] = v;
    __syncthreads();
    for (int d = 1; d < 64; d <<= 1) {
        int x = (t >= d) ? sb[t - d] : 0;
        __syncthreads();
        sb[t] += x;
        __syncthreads();
    }
    if (t < 49) g_blkoff[y][t] = sb[t] - v;
    if (t == 63) off[NN] = sb[63];
}

__global__ void scan_add() {
    int y = blockIdx.y;
    int* off = y ? g_off_b : g_off_a;
    int add = g_blkoff[y][blockIdx.x];
    int base = blockIdx.x * 1024 + threadIdx.x * 4;
#pragma unroll
    for (int i = 0; i < 4; i++) {
        int idx = base + i;
        if (idx < NN) off[idx] += add;
    }
}

__global__ void fill_kernel(const int* __restrict__ src_a, const int* __restrict__ dst_a,
                            const int* __restrict__ src_b, const int* __restrict__ dst_b) {
    int e = blockIdx.x * blockDim.x + threadIdx.x;
    if (e < EE) {
        int da = dst_a[e];
        int pa = g_off_a[da] + atomicAdd(&g_cur_a[da], 1);
        g_csr_a[pa] = src_a[e];
        int db = dst_b[e];
        int pb = g_off_b[db] + atomicAdd(&g_cur_b[db], 1);
        g_csr_b[pb] = src_b[e];
    }
}

// ---------------- input conversion fp32 -> packed + planes ----------------
__global__ void conv_kernel(const float* __restrict__ xs, const float* __restrict__ xt) {
    int i = blockIdx.x * 256 + threadIdx.x;
    int base = i * 4;
    if (base >= TOT) return;
    const float* src = blockIdx.y ? xt : xs;
    unsigned* dstP = blockIdx.y ? g_pxt : g_pxs;
    ushortT* dstH = blockIdx.y ? g_hxt : g_hxs;
    ushortT* dstL = blockIdx.y ? g_lxt : g_lxs;
    float4 v = *(const float4*)(src + base);
    uint4 o;
    o.x = pack_split(v.x); o.y = pack_split(v.y);
    o.z = pack_split(v.z); o.w = pack_split(v.w);
    *(uint4*)(dstP + base) = o;
    uint2 h, l;
    h.x = __byte_perm(o.x, o.y, 0x5410); h.y = __byte_perm(o.z, o.w, 0x5410);
    l.x = __byte_perm(o.x, o.y, 0x7632); l.y = __byte_perm(o.z, o.w, 0x7632);
    ((uint2*)dstH)[i] = h;
    ((uint2*)dstL)[i] = l;
}

// ---------------- segment mean: packed gather -> plane output ----------------
__global__ void segmean_kernel(const unsigned* __restrict__ x, const int* __restrict__ off,
                               const int* __restrict__ csr,
                               ushortT* __restrict__ outH, ushortT* __restrict__ outL) {
    int r = blockIdx.x;
    int t = threadIdx.x;  // 0..63, 4 elements each
    int s0 = off[r], s1 = off[r + 1];
    float a0 = 0.f, a1 = 0.f, a2 = 0.f, a3 = 0.f;
    for (int e = s0; e < s1; e++) {
        int src = csr[e];
        uint4 p = __ldg((const uint4*)(x + (size_t)src * DD) + t);
        a0 += unpack_val(p.x); a1 += unpack_val(p.y);
        a2 += unpack_val(p.z); a3 += unpack_val(p.w);
    }
    int cnt = s1 - s0;
    float inv = 1.0f / (float)(cnt > 0 ? cnt : 1);
    unsigned w0 = pack_split(a0 * inv), w1 = pack_split(a1 * inv);
    unsigned w2 = pack_split(a2 * inv), w3 = pack_split(a3 * inv);
    uint2 h, l;
    h.x = __byte_perm(w0, w1, 0x5410); h.y = __byte_perm(w2, w3, 0x5410);
    l.x = __byte_perm(w0, w1, 0x7632); l.y = __byte_perm(w2, w3, 0x7632);
    ((uint2*)outH)[(size_t)r * 64 + t] = h;
    ((uint2*)outL)[(size_t)r * 64 + t] = l;
}

// ---------------- weight prep: transpose + fp32 -> bf16 hi/lo split ----------------
__global__ void wprep_kernel(const float* __restrict__ Wl_st, const float* __restrict__ Wr_st,
                             const float* __restrict__ Wl_ts, const float* __restrict__ Wr_ts) {
    int m = blockIdx.y;           // 0..7
    int layer = m >> 2, t = m & 3;
    const float* base = (t == 0) ? Wl_st : (t == 1) ? Wr_st : (t == 2) ? Wl_ts : Wr_ts;
    const float* W = base + layer * 65536;
    int idx = blockIdx.x * 256 + threadIdx.x;
    int n = idx >> 8, k = idx & 255;
    float v = W[k * 256 + n];
    __nv_bfloat16 h = __float2bfloat16(v);
    float lo = v - __bfloat162float(h);
    g_wbh[m * 65536 + idx] = h;
    g_wbl[m * 65536 + idx] = __float2bfloat16(lo);
}

// ---------------- cp.async mma GEMM + bias + leaky + dropout ----------------
// C[M,256] = store( dropout( leaky( A1@W1 + A2@W2 + bias ) ) )
// A as bf16 hi/lo planes; W as bf16 hi/lo [n][k]; x*w ~= xh*wh + xh*wl + xl*wh
#define ASTRIDE 20                 // u32 per 32-k row (64B data + 16B pad)
#define TILE_U32 2560              // 128 rows * 20 u32
#define STAGE_U32 (4 * TILE_U32)   // Ah, Al, Bh, Bl
#define NSTAGE 3
#define SMEM_GEMM (NSTAGE * STAGE_U32 * 4)   // 122880 B
#define OFF_AH 0
#define OFF_AL TILE_U32
#define OFF_BH (2 * TILE_U32)
#define OFF_BL (3 * TILE_U32)

#define LDSM4(r0, r1, r2, r3, addr) \
    asm volatile("ldmatrix.sync.aligned.m8n8.x4.shared.b16 {%0,%1,%2,%3}, [%4];" \
                 : "=r"(r0), "=r"(r1), "=r"(r2), "=r"(r3) : "r"(addr))

#define MMA16816(c, a, b0, b1) \
    asm volatile("mma.sync.aligned.m16n8k16.row.col.f32.bf16.bf16.f32 " \
                 "{%0,%1,%2,%3}, {%4,%5,%6,%7}, {%8,%9}, {%0,%1,%2,%3};" \
                 : "+f"((c)[0]), "+f"((c)[1]), "+f"((c)[2]), "+f"((c)[3]) \
                 : "r"((a)[0]), "r"((a)[1]), "r"((a)[2]), "r"((a)[3]), "r"(b0), "r"(b1))

#define CP16(dst, src, nbytes) \
    asm volatile("cp.async.cg.shared.global [%0], [%1], 16, %2;" \
                 :: "r"(dst), "l"(src), "r"(nbytes))
#define CP_COMMIT() asm volatile("cp.async.commit_group;")
#define CP_WAIT1()  asm volatile("cp.async.wait_group 1;")

__global__ void __launch_bounds__(256, 1) gemm_mma(
    const ushortT* __restrict__ A1h, const ushortT* __restrict__ A1l,
    const ushortT* __restrict__ A2h, const ushortT* __restrict__ A2l,
    const __nv_bfloat16* __restrict__ W1h, const __nv_bfloat16* __restrict__ W1l,
    const __nv_bfloat16* __restrict__ W2h, const __nv_bfloat16* __restrict__ W2l,
    const float* __restrict__ bias,
    unsigned* __restrict__ outP, unsigned* __restrict__ outH, unsigned* __restrict__ outL,
    int M, unsigned dk0, unsigned dk1) {
    extern __shared__ uint32_t sm[];
    const int tid = threadIdx.x;
    const int lane = tid & 31, wid = tid >> 5;
    const int warpM = wid & 3, warpN = wid >> 2;      // 4 x 2 warps
    const int rowBase = blockIdx.y * MTILE;
    const int colBase = blockIdx.x * 128;
    const uint32_t smaddr = smem_u32(sm);

    float acc[2][8][4];
#pragma unroll
    for (int i = 0; i < 2; i++)
#pragma unroll
        for (int j = 0; j < 8; j++)
#pragma unroll
            for (int q = 0; q < 4; q++) acc[i][j][q] = 0.f;

    uint32_t aAddr[2][2], bAddr[4][2];
#pragma unroll
    for (int mt = 0; mt < 2; mt++)
#pragma unroll
        for (int ks = 0; ks < 2; ks++) {
            int row = warpM * 32 + mt * 16 + (lane & 15);
            int kOff = ks * 16 + (lane >> 4) * 8;
            aAddr[mt][ks] = smaddr + (uint32_t)(OFF_AH + row * ASTRIDE) * 4 + kOff * 2;
        }
#pragma unroll
    for (int np = 0; np < 4; np++)
#pragma unroll
        for (int ks = 0; ks < 2; ks++) {
            int n = warpN * 64 + np * 16 + (lane & 7) + (lane >> 4) * 8;
            int kOff = ks * 16 + ((lane >> 3) & 1) * 8;
            bAddr[np][ks] = smaddr + (uint32_t)(OFF_BH + n * ASTRIDE) * 4 + kOff * 2;
        }

    // issue cp.asyncs for chunk c into buffer buf
    // each 32-k row = 64 data bytes = 4 segments of 16B = 4 x 8 ushort elements
#define GISSUE(c, buf) do { \
        int mat_ = (c) >> 3; int kb_ = ((c) & 7) * 32; \
        const ushortT* Ah_ = mat_ ? A2h : A1h; \
        const ushortT* Al_ = mat_ ? A2l : A1l; \
        const ushortT* Bh_ = (const ushortT*)(mat_ ? W2h : W1h); \
        const ushortT* Bl_ = (const ushortT*)(mat_ ? W2l : W1l); \
        uint32_t stAddr_ = smaddr + (uint32_t)(buf) * (STAGE_U32 * 4); \
        _Pragma("unroll") \
        for (int j = 0; j < 8; j++) { \
            int q = j * 256 + tid; \
            int tile = q >> 9; \
            int r = (q >> 2) & 127; \
            int s = q & 3; \
            uint32_t dst = stAddr_ + (uint32_t)tile * (TILE_U32 * 4) + r * 80 + s * 16; \
            if (tile < 2) { \
                int gr = rowBase + r; \
                const ushortT* P = tile ? Al_ : Ah_; \
                int pb = (gr < M) ? 16 : 0; \
                int gc = (gr < M) ? gr : 0; \
                CP16(dst, P + (size_t)gc * 256 + kb_ + s * 8, pb); \
            } else { \
                const ushortT* P = (tile == 2) ? Bh_ : Bl_; \
                int n = colBase + r; \
                CP16(dst, P + (size_t)n * 256 + kb_ + s * 8, 16); \
            } \
        } \
    } while (0)

    GISSUE(0, 0); CP_COMMIT();
    GISSUE(1, 1); CP_COMMIT();

#pragma unroll 1
    for (int c = 0; c < 16; c++) {
        CP_WAIT1();
        __syncthreads();
        const uint32_t stOff = (uint32_t)(c % NSTAGE) * (STAGE_U32 * 4);
#pragma unroll
        for (int ks = 0; ks < 2; ks++) {
            uint32_t ah[2][4], al[2][4], bh[4][4], bl[4][4];
#pragma unroll
            for (int mt = 0; mt < 2; mt++) {
                uint32_t ad = aAddr[mt][ks] + stOff;
                LDSM4(ah[mt][0], ah[mt][1], ah[mt][2], ah[mt][3], ad);
                LDSM4(al[mt][0], al[mt][1], al[mt][2], al[mt][3], ad + (OFF_AL - OFF_AH) * 4);
            }
#pragma unroll
            for (int np = 0; np < 4; np++) {
                uint32_t bd = bAddr[np][ks] + stOff;
                LDSM4(bh[np][0], bh[np][1], bh[np][2], bh[np][3], bd);
                LDSM4(bl[np][0], bl[np][1], bl[np][2], bl[np][3], bd + (OFF_BL - OFF_BH) * 4);
            }
#pragma unroll
            for (int mt = 0; mt < 2; mt++)
#pragma unroll
                for (int nt = 0; nt < 8; nt++) {
                    int grp = nt >> 1, pr = (nt & 1) * 2;
                    MMA16816(acc[mt][nt], ah[mt], bh[grp][pr], bh[grp][pr + 1]);
                    MMA16816(acc[mt][nt], ah[mt], bl[grp][pr], bl[grp][pr + 1]);
                    MMA16816(acc[mt][nt], al[mt], bh[grp][pr], bh[grp][pr + 1]);
                }
        }
        if (c + 2 < 16) GISSUE(c + 2, (c + 2) % NSTAGE);
        CP_COMMIT();
    }

    // epilogue: bias + leaky-relu + dropout + store (packed or planes)
    const float sc = 1.0f / 0.9f;
#pragma unroll
    for (int mt = 0; mt < 2; mt++)
#pragma unroll
        for (int nt = 0; nt < 8; nt++) {
            int col = colBase + warpN * 64 + nt * 8 + (lane & 3) * 2;
            float2 bv = *(const float2*)(bias + col);
#pragma unroll
            for (int half = 0; half < 2; half++) {
                int r = rowBase + warpM * 32 + mt * 16 + (lane >> 2) + half * 8;
                if (r >= M) continue;
                float v0 = acc[mt][nt][half * 2 + 0] + bv.x;
                float v1 = acc[mt][nt][half * 2 + 1] + bv.y;
                v0 = v0 >= 0.f ? v0 : 0.01f * v0;
                v1 = v1 >= 0.f ? v1 : 0.01f * v1;
                unsigned i0 = (unsigned)r * 256u + (unsigned)col;
                unsigned q0 = jax_bits32(dk0, dk1, i0);
                unsigned q1 = jax_bits32(dk0, dk1, i0 + 1u);
                float u0 = __uint_as_float((q0 >> 9) | 0x3f800000u) - 1.0f;
                float u1 = __uint_as_float((q1 >> 9) | 0x3f800000u) - 1.0f;
                v0 = (u0 < 0.9f) ? v0 * sc : 0.0f;
                v1 = (u1 < 0.9f) ? v1 * sc : 0.0f;
                unsigned w0 = pack_split(v0), w1 = pack_split(v1);
                if (outP) {
                    *(uint2*)(outP + (size_t)r * 256 + col) = make_uint2(w0, w1);
                } else {
                    unsigned hi = __byte_perm(w0, w1, 0x5410);
                    unsigned lo = __byte_perm(w0, w1, 0x7632);
                    outH[(size_t)r * 128 + (col >> 1)] = hi;
                    outL[(size_t)r * 128 + (col >> 1)] = lo;
                }
            }
        }
}

// ---------------- output GEMM: out[50000x16] = (hi+lo)(x) @ Wout + bout ----------------
__global__ void out_kernel(const ushortT* __restrict__ xH, const ushortT* __restrict__ xL,
                           const float* __restrict__ W,
                           const float* __restrict__ b, float* __restrict__ out, int M) {
    __shared__ float Ws[256 * 16];
    __shared__ float Xs[16 * 256];
    int tid = threadIdx.x;
    int rowBase = blockIdx.x * 16;
    for (int i = tid; i < 256 * 16 / 4; i += 256)
        ((float4*)Ws)[i] = ((const float4*)W)[i];
    for (int i = tid; i < 16 * 64; i += 256) {
        int rr = i >> 6, c4 = i & 63;
        int gr = rowBase + rr;
        float4 v = make_float4(0.f, 0.f, 0.f, 0.f);
        if (gr < M) {
            uint2 h2 = ((const uint2*)xH)[(size_t)gr * 64 + c4];
            uint2 l2 = ((const uint2*)xL)[(size_t)gr * 64 + c4];
            v.x = __uint_as_float(h2.x << 16) + __uint_as_float(l2.x << 16);
            v.y = __uint_as_float(h2.x & 0xFFFF0000u) + __uint_as_float(l2.x & 0xFFFF0000u);
            v.z = __uint_as_float(h2.y << 16) + __uint_as_float(l2.y << 16);
            v.w = __uint_as_float(h2.y & 0xFFFF0000u) + __uint_as_float(l2.y & 0xFFFF0000u);
        }
        ((float4*)(Xs + rr * 256))[c4] = v;
    }
    __syncthreads();
    int rr = tid >> 4, cc = tid & 15;
    float acc = 0.f;
#pragma unroll 8
    for (int k = 0; k < 256; k++) acc += Xs[rr * 256 + k] * Ws[k * 16 + cc];
    int gr = rowBase + rr;
    if (gr < M) out[(size_t)gr * 16 + cc] = acc + b[cc];
}

// ---------------- host ----------------
extern "C" void kernel_launch(void* const* d_in, const int* in_sizes, int n_in,
                              void* d_out, int out_size) {
    const float* x_source = (const float*)d_in[0];
    const float* x_target = (const float*)d_in[1];
    const int* ei_st = (const int*)d_in[2];
    const int* ei_ts = (const int*)d_in[3];
    const float* Wl_st = (const float*)d_in[4];
    const float* Wr_st = (const float*)d_in[5];
    const float* b_st = (const float*)d_in[6];
    const float* Wl_ts = (const float*)d_in[7];
    const float* Wr_ts = (const float*)d_in[8];
    const float* b_ts = (const float*)d_in[9];
    const float* Wout = (const float*)d_in[10];
    const float* bout = (const float*)d_in[11];
    float* out = (float*)d_out;

    void* p;
    unsigned *pxs, *pxt, *pxt0;
    ushortT *hxs, *lxs, *hxt, *lxt, *hma, *lma, *hmb, *lmb, *hxs0, *lxs0, *hxs1, *lxs1;
    __nv_bfloat16 *wbh, *wbl;
    cudaGetSymbolAddress(&p, g_pxs);  pxs = (unsigned*)p;
    cudaGetSymbolAddress(&p, g_pxt);  pxt = (unsigned*)p;
    cudaGetSymbolAddress(&p, g_pxt0); pxt0 = (unsigned*)p;
    cudaGetSymbolAddress(&p, g_hxs);  hxs = (ushortT*)p;
    cudaGetSymbolAddress(&p, g_lxs);  lxs = (ushortT*)p;
    cudaGetSymbolAddress(&p, g_hxt);  hxt = (ushortT*)p;
    cudaGetSymbolAddress(&p, g_lxt);  lxt = (ushortT*)p;
    cudaGetSymbolAddress(&p, g_hma);  hma = (ushortT*)p;
    cudaGetSymbolAddress(&p, g_lma);  lma = (ushortT*)p;
    cudaGetSymbolAddress(&p, g_hmb);  hmb = (ushortT*)p;
    cudaGetSymbolAddress(&p, g_lmb);  lmb = (ushortT*)p;
    cudaGetSymbolAddress(&p, g_hxs0); hxs0 = (ushortT*)p;
    cudaGetSymbolAddress(&p, g_lxs0); lxs0 = (ushortT*)p;
    cudaGetSymbolAddress(&p, g_hxs1); hxs1 = (ushortT*)p;
    cudaGetSymbolAddress(&p, g_lxs1); lxs1 = (ushortT*)p;
    cudaGetSymbolAddress(&p, g_wbh);  wbh = (__nv_bfloat16*)p;
    cudaGetSymbolAddress(&p, g_wbl);  wbl = (__nv_bfloat16*)p;
    int *off_a, *off_b, *csr_a, *csr_b;
    cudaGetSymbolAddress(&p, g_off_a); off_a = (int*)p;
    cudaGetSymbolAddress(&p, g_off_b); off_b = (int*)p;
    cudaGetSymbolAddress(&p, g_csr_a); csr_a = (int*)p;
    cudaGetSymbolAddress(&p, g_csr_b); csr_b = (int*)p;

    cudaFuncSetAttribute(gemm_mma, cudaFuncAttributeMaxDynamicSharedMemorySize, SMEM_GEMM);

    const int* src_st = ei_st;
    const int* dst_st = ei_st + EE;
    const int* src_ts = ei_ts;
    const int* dst_ts = ei_ts + EE;

    // dropout keys: fold_in(key(42)=(0,42), d); d=0 -> xs0, d=1 -> xt0, d=2 -> xs1
    unsigned dkeys[3][2];
    for (int d = 0; d < 3; d++)
        tf2x32(0u, 42u, 0u, (unsigned)d, dkeys[d][0], dkeys[d][1]);

    wprep_kernel<<<dim3(256, 8), 256>>>(Wl_st, Wr_st, Wl_ts, Wr_ts);
    conv_kernel<<<dim3(12500, 2), 256>>>(x_source, x_target);
    zero_kernel<<<(NN + 255) / 256, 256>>>();
    count_kernel<<<(EE + 255) / 256, 256>>>(dst_st, dst_ts);
    scan_pre<<<dim3(49, 2), 256>>>();
    scan_mid<<<dim3(1, 2), 64>>>();
    scan_add<<<dim3(49, 2), 256>>>();
    fill_kernel<<<(EE + 255) / 256, 256>>>(src_st, dst_st, src_ts, dst_ts);

    const int M64K = 65536;
    dim3 gGrid(2, NBLKY);

    // ---- layer 0 ----
    segmean_kernel<<<NN, 64>>>(pxs, off_a, csr_a, hma, lma);   // m_t
    segmean_kernel<<<NN, 64>>>(pxt, off_b, csr_b, hmb, lmb);   // m_s
    // new_t = m_t@Wl_st + x_t@Wr_st (+b_st) -> xt0 (packed; consumed by segmean)
    gemm_mma<<<gGrid, 256, SMEM_GEMM>>>(hma, lma, hxt, lxt,
                                        wbh + 0 * M64K, wbl + 0 * M64K,
                                        wbh + 1 * M64K, wbl + 1 * M64K, b_st,
                                        pxt0, nullptr, nullptr, NN,
                                        dkeys[1][0], dkeys[1][1]);
    // new_s = m_s@Wl_ts + x_s@Wr_ts (+b_ts) -> xs0 (planes; consumed by gemm)
    gemm_mma<<<gGrid, 256, SMEM_GEMM>>>(hmb, lmb, hxs, lxs,
                                        wbh + 2 * M64K, wbl + 2 * M64K,
                                        wbh + 3 * M64K, wbl + 3 * M64K, b_ts,
                                        nullptr, (unsigned*)hxs0, (unsigned*)lxs0, NN,
                                        dkeys[0][0], dkeys[0][1]);

    // ---- layer 1 (target branch is dead) ----
    segmean_kernel<<<NN, 64>>>(pxt0, off_b, csr_b, hma, lma);  // m_s (layer 1)
    gemm_mma<<<gGrid, 256, SMEM_GEMM>>>(hma, lma, hxs0, lxs0,
                                        wbh + 6 * M64K, wbl + 6 * M64K,
                                        wbh + 7 * M64K, wbl + 7 * M64K, b_ts + 256,
                                        nullptr, (unsigned*)hxs1, (unsigned*)lxs1, NN,
                                        dkeys[2][0], dkeys[2][1]);

    // ---- output projection ----
    out_kernel<<<(NN + 15) / 16, 256>>>(hxs1, lxs1, Wout, bout, out, NN);
}

// round 8
// speedup vs baseline: 1.0803x; 1.0803x over previous
#include <cuda_runtime.h>
#include <cuda_bf16.h>
#include <cstdint>

#define NN 50000
#define DD 256
#define EE 320000
#define TOT (NN * DD)
#define MTILE 128
#define NBLKY ((NN + MTILE - 1) / MTILE)   // 391

// ---------------- scratch (static __device__ — no allocation allowed) ----------------
__device__ int g_cnt_a[NN], g_cnt_b[NN], g_cur_a[NN], g_cur_b[NN];
__device__ int g_off_a[NN + 1], g_off_b[NN + 1];
__device__ int g_csr_a[EE], g_csr_b[EE];
__device__ int g_blk[2][49], g_blkoff[2][49];
// packed u32 (hi|lo<<16) bf16-split activations
__device__ unsigned g_pxs[TOT], g_pxt[TOT];
__device__ unsigned g_pma[TOT], g_pmb[TOT];
__device__ unsigned g_pxt0[TOT], g_pxs0[TOT], g_pxs1[TOT];
// pre-transposed bf16 hi/lo weights: 8 matrices of [n=256][k=256]
__device__ __nv_bfloat16 g_wbh[8 * 65536], g_wbl[8 * 65536];

// ---------------- threefry-2x32 (exactly JAX's) ----------------
__host__ __device__ __forceinline__ unsigned rotl32(unsigned x, int d) {
    return (x << d) | (x >> (32 - d));
}

__host__ __device__ __forceinline__ void tf2x32(unsigned k0, unsigned k1,
                                                unsigned x0, unsigned x1,
                                                unsigned& o0, unsigned& o1) {
    unsigned ks2 = k0 ^ k1 ^ 0x1BD11BDAu;
    x0 += k0; x1 += k1;
#define TF_ROUND(r) { x0 += x1; x1 = rotl32(x1, r); x1 ^= x0; }
    TF_ROUND(13) TF_ROUND(15) TF_ROUND(26) TF_ROUND(6)
    x0 += k1;  x1 += ks2 + 1u;
    TF_ROUND(17) TF_ROUND(29) TF_ROUND(16) TF_ROUND(24)
    x0 += ks2; x1 += k0 + 2u;
    TF_ROUND(13) TF_ROUND(15) TF_ROUND(26) TF_ROUND(6)
    x0 += k0;  x1 += k1 + 3u;
    TF_ROUND(17) TF_ROUND(29) TF_ROUND(16) TF_ROUND(24)
    x0 += k1;  x1 += ks2 + 4u;
    TF_ROUND(13) TF_ROUND(15) TF_ROUND(26) TF_ROUND(6)
    x0 += ks2; x1 += k0 + 5u;
#undef TF_ROUND
    o0 = x0; o1 = x1;
}

__device__ __forceinline__ unsigned jax_bits32(unsigned k0, unsigned k1, unsigned i) {
    unsigned o0, o1;
    tf2x32(k0, k1, 0u, i, o0, o1);
    return o0 ^ o1;
}

__device__ __forceinline__ uint32_t smem_u32(const void* p) {
    uint32_t a;
    asm("{ .reg .u64 t; cvta.to.shared.u64 t, %1; cvt.u32.u64 %0, t; }" : "=r"(a) : "l"(p));
    return a;
}

// ---------------- packed bf16-split helpers ----------------
__device__ __forceinline__ unsigned pack_split(float v) {
    __nv_bfloat16 h = __float2bfloat16(v);
    unsigned hu = (unsigned)*(unsigned short*)&h;
    float hf = __uint_as_float(hu << 16);
    __nv_bfloat16 l = __float2bfloat16(v - hf);
    unsigned lu = (unsigned)*(unsigned short*)&l;
    return hu | (lu << 16);
}

__device__ __forceinline__ float unpack_val(unsigned p) {
    return __uint_as_float(p << 16) + __uint_as_float(p & 0xFFFF0000u);
}

// ---------------- CSR build ----------------
__global__ void zero_kernel() {
    int i = blockIdx.x * blockDim.x + threadIdx.x;
    if (i < NN) { g_cnt_a[i] = 0; g_cnt_b[i] = 0; g_cur_a[i] = 0; g_cur_b[i] = 0; }
}

__global__ void count_kernel(const int* __restrict__ dst_a, const int* __restrict__ dst_b) {
    int e = blockIdx.x * blockDim.x + threadIdx.x;
    if (e < EE) {
        atomicAdd(&g_cnt_a[dst_a[e]], 1);
        atomicAdd(&g_cnt_b[dst_b[e]], 1);
    }
}

__global__ void scan_pre() {
    int y = blockIdx.y;
    const int* cnt = y ? g_cnt_b : g_cnt_a;
    int* off = y ? g_off_b : g_off_a;
    __shared__ int sb[256];
    int t = threadIdx.x;
    int base = blockIdx.x * 1024 + t * 4;
    int v[4]; int s = 0;
#pragma unroll
    for (int i = 0; i < 4; i++) {
        int idx = base + i;
        v[i] = (idx < NN) ? cnt[idx] : 0;
        s += v[i];
    }
    sb[t] = s;
    __syncthreads();
    for (int d = 1; d < 256; d <<= 1) {
        int x = (t >= d) ? sb[t - d] : 0;
        __syncthreads();
        sb[t] += x;
        __syncthreads();
    }
    int run = sb[t] - s;
#pragma unroll
    for (int i = 0; i < 4; i++) {
        int idx = base + i;
        if (idx < NN) off[idx] = run;
        run += v[i];
    }
    if (t == 255) g_blk[y][blockIdx.x] = sb[255];
}

__global__ void scan_mid() {
    int y = blockIdx.y;
    int* off = y ? g_off_b : g_off_a;
    __shared__ int sb[64];
    int t = threadIdx.x;
    int v = (t < 49) ? g_blk[y][t] : 0;
    sb[t] = v;
    __syncthreads();
    for (int d = 1; d < 64; d <<= 1) {
        int x = (t >= d) ? sb[t - d] : 0;
        __syncthreads();
        sb[t] += x;
        __syncthreads();
    }
    if (t < 49) g_blkoff[y][t] = sb[t] - v;
    if (t == 63) off[NN] = sb[63];
}

__global__ void scan_add() {
    int y = blockIdx.y;
    int* off = y ? g_off_b : g_off_a;
    int add = g_blkoff[y][blockIdx.x];
    int base = blockIdx.x * 1024 + threadIdx.x * 4;
#pragma unroll
    for (int i = 0; i < 4; i++) {
        int idx = base + i;
        if (idx < NN) off[idx] += add;
    }
}

__global__ void fill_kernel(const int* __restrict__ src_a, const int* __restrict__ dst_a,
                            const int* __restrict__ src_b, const int* __restrict__ dst_b) {
    int e = blockIdx.x * blockDim.x + threadIdx.x;
    if (e < EE) {
        int da = dst_a[e];
        int pa = g_off_a[da] + atomicAdd(&g_cur_a[da], 1);
        g_csr_a[pa] = src_a[e];
        int db = dst_b[e];
        int pb = g_off_b[db] + atomicAdd(&g_cur_b[db], 1);
        g_csr_b[pb] = src_b[e];
    }
}

// ---------------- input conversion fp32 -> packed ----------------
__global__ void conv_kernel(const float* __restrict__ xs, const float* __restrict__ xt) {
    int i = blockIdx.x * 256 + threadIdx.x;
    int base = i * 4;
    if (base >= TOT) return;
    const float* src = blockIdx.y ? xt : xs;
    unsigned* dst = blockIdx.y ? g_pxt : g_pxs;
    float4 v = *(const float4*)(src + base);
    uint4 o;
    o.x = pack_split(v.x); o.y = pack_split(v.y);
    o.z = pack_split(v.z); o.w = pack_split(v.w);
    *(uint4*)(dst + base) = o;
}

// ---------------- segment mean over packed activations (dual via blockIdx.y) ----------------
__global__ void segmean2_kernel(const unsigned* __restrict__ x0, const int* __restrict__ off0,
                                const int* __restrict__ csr0, unsigned* __restrict__ out0,
                                const unsigned* __restrict__ x1, const int* __restrict__ off1,
                                const int* __restrict__ csr1, unsigned* __restrict__ out1) {
    int y = blockIdx.y;
    const unsigned* x = y ? x1 : x0;
    const int* off = y ? off1 : off0;
    const int* csr = y ? csr1 : csr0;
    unsigned* out = y ? out1 : out0;
    int r = blockIdx.x;
    int t = threadIdx.x;  // 0..63, 4 elements each
    int s0 = off[r], s1 = off[r + 1];
    float a0 = 0.f, a1 = 0.f, a2 = 0.f, a3 = 0.f;
    for (int e = s0; e < s1; e++) {
        int src = csr[e];
        uint4 p = __ldg((const uint4*)(x + (size_t)src * DD) + t);
        a0 += unpack_val(p.x); a1 += unpack_val(p.y);
        a2 += unpack_val(p.z); a3 += unpack_val(p.w);
    }
    int cnt = s1 - s0;
    float inv = 1.0f / (float)(cnt > 0 ? cnt : 1);
    uint4 o;
    o.x = pack_split(a0 * inv); o.y = pack_split(a1 * inv);
    o.z = pack_split(a2 * inv); o.w = pack_split(a3 * inv);
    ((uint4*)(out + (size_t)r * DD))[t] = o;
}

// ---------------- weight prep: transpose + fp32 -> bf16 hi/lo split ----------------
__global__ void wprep_kernel(const float* __restrict__ Wl_st, const float* __restrict__ Wr_st,
                             const float* __restrict__ Wl_ts, const float* __restrict__ Wr_ts) {
    int m = blockIdx.y;           // 0..7
    int layer = m >> 2, t = m & 3;
    const float* base = (t == 0) ? Wl_st : (t == 1) ? Wr_st : (t == 2) ? Wl_ts : Wr_ts;
    const float* W = base + layer * 65536;
    int idx = blockIdx.x * 256 + threadIdx.x;
    int n = idx >> 8, k = idx & 255;
    float v = W[k * 256 + n];
    __nv_bfloat16 h = __float2bfloat16(v);
    float lo = v - __bfloat162float(h);
    g_wbh[m * 65536 + idx] = h;
    g_wbl[m * 65536 + idx] = __float2bfloat16(lo);
}

// ---------------- mma.sync bf16-split fused dual-GEMM + bias + leaky + dropout ----------------
// 3-stage smem rotation, ONE __syncthreads per k-chunk.
#define ASTRIDE 20
#define ST_U32 10240          // 4 tiles * 128 rows * 20 u32 (one stage)
#define OFF_AH 0
#define OFF_AL 2560
#define OFF_BH 5120
#define OFF_BL 7680
#define SMEM_GEMM (3 * ST_U32 * 4)   // 122880 B

#define LDSM4(r0, r1, r2, r3, addr) \
    asm volatile("ldmatrix.sync.aligned.m8n8.x4.shared.b16 {%0,%1,%2,%3}, [%4];" \
                 : "=r"(r0), "=r"(r1), "=r"(r2), "=r"(r3) : "r"(addr))

#define MMA16816(c, a, b0, b1) \
    asm volatile("mma.sync.aligned.m16n8k16.row.col.f32.bf16.bf16.f32 " \
                 "{%0,%1,%2,%3}, {%4,%5,%6,%7}, {%8,%9}, {%0,%1,%2,%3};" \
                 : "+f"((c)[0]), "+f"((c)[1]), "+f"((c)[2]), "+f"((c)[3]) \
                 : "r"((a)[0]), "r"((a)[1]), "r"((a)[2]), "r"((a)[3]), "r"(b0), "r"(b1))

struct GArgs {
    const unsigned *A1, *A2;
    const __nv_bfloat16 *W1h, *W1l, *W2h, *W2l;
    const float* bias;
    unsigned* outC;
    unsigned dk0, dk1;
};

__global__ void __launch_bounds__(256, 1) gemm_mma(GArgs ga, GArgs gb, int M) {
    extern __shared__ uint32_t sm[];
    const GArgs g = blockIdx.z ? gb : ga;
    const unsigned* __restrict__ A1 = g.A1;
    const unsigned* __restrict__ A2 = g.A2;
    const __nv_bfloat16* __restrict__ W1h = g.W1h;
    const __nv_bfloat16* __restrict__ W1l = g.W1l;
    const __nv_bfloat16* __restrict__ W2h = g.W2h;
    const __nv_bfloat16* __restrict__ W2l = g.W2l;
    const float* __restrict__ bias = g.bias;
    unsigned* __restrict__ C = g.outC;
    const unsigned dk0 = g.dk0, dk1 = g.dk1;

    const int tid = threadIdx.x;
    const int lane = tid & 31, wid = tid >> 5;
    const int warpM = wid & 3, warpN = wid >> 2;      // 4 x 2 warps
    const int rowBase = blockIdx.y * MTILE;
    const int colBase = blockIdx.x * 128;
    const uint32_t smaddr = smem_u32(sm);

    float acc[2][8][4];
#pragma unroll
    for (int i = 0; i < 2; i++)
#pragma unroll
        for (int j = 0; j < 8; j++)
#pragma unroll
            for (int q = 0; q < 4; q++) acc[i][j][q] = 0.f;

    uint4 aReg[4];
    uint4 bReg[4];

    uint32_t aAddr[2][2], bAddr[4][2];
#pragma unroll
    for (int mt = 0; mt < 2; mt++)
#pragma unroll
        for (int ks = 0; ks < 2; ks++) {
            int row = warpM * 32 + mt * 16 + (lane & 15);
            int kOff = ks * 16 + (lane >> 4) * 8;
            aAddr[mt][ks] = smaddr + (uint32_t)(OFF_AH + row * ASTRIDE + (kOff >> 1)) * 4;
        }
#pragma unroll
    for (int np = 0; np < 4; np++)
#pragma unroll
        for (int ks = 0; ks < 2; ks++) {
            int n = warpN * 64 + np * 16 + (lane & 7) + (lane >> 4) * 8;
            int kOff = ks * 16 + ((lane >> 3) & 1) * 8;
            bAddr[np][ks] = smaddr + (uint32_t)(OFF_BH + n * ASTRIDE + (kOff >> 1)) * 4;
        }

#define GLOAD(c) do { \
        int mat_ = (c) >> 3; int kb_ = ((c) & 7) * 32; \
        const unsigned* A_ = mat_ ? A2 : A1; \
        const __nv_bfloat16* Bh_ = mat_ ? W2h : W1h; \
        const __nv_bfloat16* Bl_ = mat_ ? W2l : W1l; \
        _Pragma("unroll") \
        for (int j = 0; j < 4; j++) { \
            int idx = tid + j * 256; \
            int r = idx >> 3, kq = (idx & 7) * 4; \
            int gr = rowBase + r; \
            aReg[j] = (gr < M) ? *(const uint4*)(A_ + (size_t)gr * 256 + kb_ + kq) \
                               : make_uint4(0u, 0u, 0u, 0u); \
        } \
        _Pragma("unroll") \
        for (int j = 0; j < 2; j++) { \
            int idx = tid + j * 256; \
            int n = idx >> 2, ko = (idx & 3) * 8; \
            bReg[j]     = *(const uint4*)(Bh_ + (size_t)(colBase + n) * 256 + kb_ + ko); \
            bReg[2 + j] = *(const uint4*)(Bl_ + (size_t)(colBase + n) * 256 + kb_ + ko); \
        } \
    } while (0)

#define SSTORE(st) do { \
        uint32_t* base_ = sm + (st) * ST_U32; \
        _Pragma("unroll") \
        for (int j = 0; j < 4; j++) { \
            int idx = tid + j * 256; \
            int r = idx >> 3, kq = (idx & 7) * 4; \
            uint4 p = aReg[j]; \
            uint32_t ah01 = __byte_perm(p.x, p.y, 0x5410); \
            uint32_t al01 = __byte_perm(p.x, p.y, 0x7632); \
            uint32_t ah23 = __byte_perm(p.z, p.w, 0x5410); \
            uint32_t al23 = __byte_perm(p.z, p.w, 0x7632); \
            uint32_t off = (uint32_t)(r * ASTRIDE + (kq >> 1)); \
            base_[OFF_AH + off]     = ah01; \
            base_[OFF_AH + off + 1] = ah23; \
            base_[OFF_AL + off]     = al01; \
            base_[OFF_AL + off + 1] = al23; \
        } \
        _Pragma("unroll") \
        for (int j = 0; j < 2; j++) { \
            int idx = tid + j * 256; \
            int n = idx >> 2, ko = (idx & 3) * 8; \
            uint32_t off = (uint32_t)(n * ASTRIDE + (ko >> 1)); \
            *(uint4*)(base_ + OFF_BH + off) = bReg[j]; \
            *(uint4*)(base_ + OFF_BL + off) = bReg[2 + j]; \
        } \
    } while (0)

    GLOAD(0);
    SSTORE(0);
    __syncthreads();

#pragma unroll 1
    for (int c = 0; c < 16; c++) {
        if (c < 15) GLOAD(c + 1);
        const uint32_t stOff = (uint32_t)(c % 3) * (ST_U32 * 4);
#pragma unroll
        for (int ks = 0; ks < 2; ks++) {
            uint32_t ah[2][4], al[2][4], bh[4][4], bl[4][4];
#pragma unroll
            for (int mt = 0; mt < 2; mt++) {
                uint32_t ad = aAddr[mt][ks] + stOff;
                LDSM4(ah[mt][0], ah[mt][1], ah[mt][2], ah[mt][3], ad);
                LDSM4(al[mt][0], al[mt][1], al[mt][2], al[mt][3], ad + (OFF_AL - OFF_AH) * 4);
            }
#pragma unroll
            for (int np = 0; np < 4; np++) {
                uint32_t bd = bAddr[np][ks] + stOff;
                LDSM4(bh[np][0], bh[np][1], bh[np][2], bh[np][3], bd);
                LDSM4(bl[np][0], bl[np][1], bl[np][2], bl[np][3], bd + (OFF_BL - OFF_BH) * 4);
            }
#pragma unroll
            for (int mt = 0; mt < 2; mt++)
#pragma unroll
                for (int nt = 0; nt < 8; nt++) {
                    int grp = nt >> 1, pr = (nt & 1) * 2;
                    MMA16816(acc[mt][nt], ah[mt], bh[grp][pr], bh[grp][pr + 1]);
                    MMA16816(acc[mt][nt], ah[mt], bl[grp][pr], bl[grp][pr + 1]);
                    MMA16816(acc[mt][nt], al[mt], bh[grp][pr], bh[grp][pr + 1]);
                }
        }
        if (c < 15) SSTORE((c + 1) % 3);
        __syncthreads();
    }

    // epilogue: bias + leaky-relu + dropout + pack, store packed u32
    const float sc = 1.0f / 0.9f;
#pragma unroll
    for (int mt = 0; mt < 2; mt++)
#pragma unroll
        for (int nt = 0; nt < 8; nt++) {
            int col = colBase + warpN * 64 + nt * 8 + (lane & 3) * 2;
            float2 bv = *(const float2*)(bias + col);
#pragma unroll
            for (int half = 0; half < 2; half++) {
                int r = rowBase + warpM * 32 + mt * 16 + (lane >> 2) + half * 8;
                if (r >= M) continue;
                float v0 = acc[mt][nt][half * 2 + 0] + bv.x;
                float v1 = acc[mt][nt][half * 2 + 1] + bv.y;
                v0 = v0 >= 0.f ? v0 : 0.01f * v0;
                v1 = v1 >= 0.f ? v1 : 0.01f * v1;
                unsigned i0 = (unsigned)r * 256u + (unsigned)col;
                unsigned q0 = jax_bits32(dk0, dk1, i0);
                unsigned q1 = jax_bits32(dk0, dk1, i0 + 1u);
                float u0 = __uint_as_float((q0 >> 9) | 0x3f800000u) - 1.0f;
                float u1 = __uint_as_float((q1 >> 9) | 0x3f800000u) - 1.0f;
                v0 = (u0 < 0.9f) ? v0 * sc : 0.0f;
                v1 = (u1 < 0.9f) ? v1 * sc : 0.0f;
                *(uint2*)(C + (size_t)r * 256 + col) = make_uint2(pack_split(v0), pack_split(v1));
            }
        }
}

// ---------------- output GEMM: out[50000x16] = unpack(x) @ Wout + bout ----------------
__global__ void out_kernel(const unsigned* __restrict__ x, const float* __restrict__ W,
                           const float* __restrict__ b, float* __restrict__ out, int M) {
    __shared__ float Ws[256 * 16];
    __shared__ float Xs[16 * 256];
    int tid = threadIdx.x;
    int rowBase = blockIdx.x * 16;
    for (int i = tid; i < 256 * 16 / 4; i += 256)
        ((float4*)Ws)[i] = ((const float4*)W)[i];
    for (int i = tid; i < 16 * 64; i += 256) {
        int rr = i >> 6, c4 = i & 63;
        int gr = rowBase + rr;
        float4 v = make_float4(0.f, 0.f, 0.f, 0.f);
        if (gr < M) {
            uint4 p = ((const uint4*)(x + (size_t)gr * 256))[c4];
            v.x = unpack_val(p.x); v.y = unpack_val(p.y);
            v.z = unpack_val(p.z); v.w = unpack_val(p.w);
        }
        ((float4*)(Xs + rr * 256))[c4] = v;
    }
    __syncthreads();
    int rr = tid >> 4, cc = tid & 15;
    float acc = 0.f;
#pragma unroll 8
    for (int k = 0; k < 256; k++) acc += Xs[rr * 256 + k] * Ws[k * 16 + cc];
    int gr = rowBase + rr;
    if (gr < M) out[(size_t)gr * 16 + cc] = acc + b[cc];
}

// ---------------- host ----------------
extern "C" void kernel_launch(void* const* d_in, const int* in_sizes, int n_in,
                              void* d_out, int out_size) {
    const float* x_source = (const float*)d_in[0];
    const float* x_target = (const float*)d_in[1];
    const int* ei_st = (const int*)d_in[2];
    const int* ei_ts = (const int*)d_in[3];
    const float* Wl_st = (const float*)d_in[4];
    const float* Wr_st = (const float*)d_in[5];
    const float* b_st = (const float*)d_in[6];
    const float* Wl_ts = (const float*)d_in[7];
    const float* Wr_ts = (const float*)d_in[8];
    const float* b_ts = (const float*)d_in[9];
    const float* Wout = (const float*)d_in[10];
    const float* bout = (const float*)d_in[11];
    float* out = (float*)d_out;

    void* p;
    unsigned *pxs, *pxt, *pma, *pmb, *pxt0, *pxs0, *pxs1;
    __nv_bfloat16 *wbh, *wbl;
    cudaGetSymbolAddress(&p, g_pxs);  pxs = (unsigned*)p;
    cudaGetSymbolAddress(&p, g_pxt);  pxt = (unsigned*)p;
    cudaGetSymbolAddress(&p, g_pma);  pma = (unsigned*)p;
    cudaGetSymbolAddress(&p, g_pmb);  pmb = (unsigned*)p;
    cudaGetSymbolAddress(&p, g_pxt0); pxt0 = (unsigned*)p;
    cudaGetSymbolAddress(&p, g_pxs0); pxs0 = (unsigned*)p;
    cudaGetSymbolAddress(&p, g_pxs1); pxs1 = (unsigned*)p;
    cudaGetSymbolAddress(&p, g_wbh);  wbh = (__nv_bfloat16*)p;
    cudaGetSymbolAddress(&p, g_wbl);  wbl = (__nv_bfloat16*)p;
    int *off_a, *off_b, *csr_a, *csr_b;
    cudaGetSymbolAddress(&p, g_off_a); off_a = (int*)p;
    cudaGetSymbolAddress(&p, g_off_b); off_b = (int*)p;
    cudaGetSymbolAddress(&p, g_csr_a); csr_a = (int*)p;
    cudaGetSymbolAddress(&p, g_csr_b); csr_b = (int*)p;

    cudaFuncSetAttribute(gemm_mma, cudaFuncAttributeMaxDynamicSharedMemorySize, SMEM_GEMM);

    const int* src_st = ei_st;
    const int* dst_st = ei_st + EE;
    const int* src_ts = ei_ts;
    const int* dst_ts = ei_ts + EE;

    // dropout keys: fold_in(key(42)=(0,42), d); d=0 -> xs0, d=1 -> xt0, d=2 -> xs1
    unsigned dkeys[3][2];
    for (int d = 0; d < 3; d++)
        tf2x32(0u, 42u, 0u, (unsigned)d, dkeys[d][0], dkeys[d][1]);

    wprep_kernel<<<dim3(256, 8), 256>>>(Wl_st, Wr_st, Wl_ts, Wr_ts);
    conv_kernel<<<dim3(12500, 2), 256>>>(x_source, x_target);
    zero_kernel<<<(NN + 255) / 256, 256>>>();
    count_kernel<<<(EE + 255) / 256, 256>>>(dst_st, dst_ts);
    scan_pre<<<dim3(49, 2), 256>>>();
    scan_mid<<<dim3(1, 2), 64>>>();
    scan_add<<<dim3(49, 2), 256>>>();
    fill_kernel<<<(EE + 255) / 256, 256>>>(src_st, dst_st, src_ts, dst_ts);

    const int M64K = 65536;

    // ---- layer 0: both segmeans in one launch, both gemms in one launch ----
    segmean2_kernel<<<dim3(NN, 2), 64>>>(pxs, off_a, csr_a, pma,
                                         pxt, off_b, csr_b, pmb);
    GArgs gA, gB;
    // z=0: new_t = m_t@Wl_st + x_t@Wr_st + b_st -> pxt0 (key d=1)
    gA.A1 = pma; gA.A2 = pxt;
    gA.W1h = wbh + 0 * M64K; gA.W1l = wbl + 0 * M64K;
    gA.W2h = wbh + 1 * M64K; gA.W2l = wbl + 1 * M64K;
    gA.bias = b_st; gA.outC = pxt0; gA.dk0 = dkeys[1][0]; gA.dk1 = dkeys[1][1];
    // z=1: new_s = m_s@Wl_ts + x_s@Wr_ts + b_ts -> pxs0 (key d=0)
    gB.A1 = pmb; gB.A2 = pxs;
    gB.W1h = wbh + 2 * M64K; gB.W1l = wbl + 2 * M64K;
    gB.W2h = wbh + 3 * M64K; gB.W2l = wbl + 3 * M64K;
    gB.bias = b_ts; gB.outC = pxs0; gB.dk0 = dkeys[0][0]; gB.dk1 = dkeys[0][1];
    gemm_mma<<<dim3(2, NBLKY, 2), 256, SMEM_GEMM>>>(gA, gB, NN);

    // ---- layer 1 (target branch is dead) ----
    segmean2_kernel<<<dim3(NN, 1), 64>>>(pxt0, off_b, csr_b, pma,
                                         pxt0, off_b, csr_b, pma);
    GArgs gC;
    gC.A1 = pma; gC.A2 = pxs0;
    gC.W1h = wbh + 6 * M64K; gC.W1l = wbl + 6 * M64K;
    gC.W2h = wbh + 7 * M64K; gC.W2l = wbl + 7 * M64K;
    gC.bias = b_ts + 256; gC.outC = pxs1; gC.dk0 = dkeys[2][0]; gC.dk1 = dkeys[2][1];
    gemm_mma<<<dim3(2, NBLKY, 1), 256, SMEM_GEMM>>>(gC, gC, NN);

    // ---- output projection ----
    out_kernel<<<(NN + 15) / 16, 256>>>(pxs1, Wout, bout, out, NN);
}

// round 9
// speedup vs baseline: 1.3981x; 1.2942x over previous
#include <cuda_runtime.h>
#include <cuda_fp16.h>
#include <cstdint>

#define NN 50000
#define DD 256
#define EE 320000
#define TOT (NN * DD)
#define MTILE 128
#define NBLKY ((NN + MTILE - 1) / MTILE)   // 391

// ---------------- scratch (static __device__ — no allocation allowed) ----------------
__device__ int g_cnt_a[NN], g_cnt_b[NN], g_cur_a[NN], g_cur_b[NN];
__device__ int g_off_a[NN + 1], g_off_b[NN + 1];
__device__ int g_csr_a[EE], g_csr_b[EE];
__device__ int g_blk[2][49], g_blkoff[2][49];
// packed u32 (fp16 hi | fp16 lo<<16) split activations: value = hi + lo (~2^-21 exact)
__device__ unsigned g_pxs[TOT], g_pxt[TOT];
__device__ unsigned g_pma[TOT], g_pmb[TOT];
__device__ unsigned g_pxt0[TOT], g_pxs0[TOT], g_pxs1[TOT];
// pre-transposed fp16 weights (hi only — W-low term dropped): 8 matrices [n=256][k=256]
__device__ __half g_wfh[8 * 65536];

// ---------------- threefry-2x32 (exactly JAX's) ----------------
__host__ __device__ __forceinline__ unsigned rotl32(unsigned x, int d) {
    return (x << d) | (x >> (32 - d));
}

__host__ __device__ __forceinline__ void tf2x32(unsigned k0, unsigned k1,
                                                unsigned x0, unsigned x1,
                                                unsigned& o0, unsigned& o1) {
    unsigned ks2 = k0 ^ k1 ^ 0x1BD11BDAu;
    x0 += k0; x1 += k1;
#define TF_ROUND(r) { x0 += x1; x1 = rotl32(x1, r); x1 ^= x0; }
    TF_ROUND(13) TF_ROUND(15) TF_ROUND(26) TF_ROUND(6)
    x0 += k1;  x1 += ks2 + 1u;
    TF_ROUND(17) TF_ROUND(29) TF_ROUND(16) TF_ROUND(24)
    x0 += ks2; x1 += k0 + 2u;
    TF_ROUND(13) TF_ROUND(15) TF_ROUND(26) TF_ROUND(6)
    x0 += k0;  x1 += k1 + 3u;
    TF_ROUND(17) TF_ROUND(29) TF_ROUND(16) TF_ROUND(24)
    x0 += k1;  x1 += ks2 + 4u;
    TF_ROUND(13) TF_ROUND(15) TF_ROUND(26) TF_ROUND(6)
    x0 += ks2; x1 += k0 + 5u;
#undef TF_ROUND
    o0 = x0; o1 = x1;
}

__device__ __forceinline__ unsigned jax_bits32(unsigned k0, unsigned k1, unsigned i) {
    unsigned o0, o1;
    tf2x32(k0, k1, 0u, i, o0, o1);
    return o0 ^ o1;
}

__device__ __forceinline__ uint32_t smem_u32(const void* p) {
    uint32_t a;
    asm("{ .reg .u64 t; cvta.to.shared.u64 t, %1; cvt.u32.u64 %0, t; }" : "=r"(a) : "l"(p));
    return a;
}

// ---------------- packed fp16-split helpers ----------------
__device__ __forceinline__ unsigned pack_split(float v) {
    __half h = __float2half_rn(v);
    float hf = __half2float(h);
    __half l = __float2half_rn(v - hf);
    return (unsigned)__half_as_ushort(h) | ((unsigned)__half_as_ushort(l) << 16);
}

__device__ __forceinline__ float unpack_val(unsigned p) {
    __half h = __ushort_as_half((unsigned short)(p & 0xFFFFu));
    __half l = __ushort_as_half((unsigned short)(p >> 16));
    return __half2float(h) + __half2float(l);
}

// ---------------- CSR build ----------------
__global__ void zero_kernel() {
    int i = blockIdx.x * blockDim.x + threadIdx.x;
    if (i < NN) { g_cnt_a[i] = 0; g_cnt_b[i] = 0; g_cur_a[i] = 0; g_cur_b[i] = 0; }
}

__global__ void count_kernel(const int* __restrict__ dst_a, const int* __restrict__ dst_b) {
    int e = blockIdx.x * blockDim.x + threadIdx.x;
    if (e < EE) {
        atomicAdd(&g_cnt_a[dst_a[e]], 1);
        atomicAdd(&g_cnt_b[dst_b[e]], 1);
    }
}

__global__ void scan_pre() {
    int y = blockIdx.y;
    const int* cnt = y ? g_cnt_b : g_cnt_a;
    int* off = y ? g_off_b : g_off_a;
    __shared__ int sb[256];
    int t = threadIdx.x;
    int base = blockIdx.x * 1024 + t * 4;
    int v[4]; int s = 0;
#pragma unroll
    for (int i = 0; i < 4; i++) {
        int idx = base + i;
        v[i] = (idx < NN) ? cnt[idx] : 0;
        s += v[i];
    }
    sb[t] = s;
    __syncthreads();
    for (int d = 1; d < 256; d <<= 1) {
        int x = (t >= d) ? sb[t - d] : 0;
        __syncthreads();
        sb[t] += x;
        __syncthreads();
    }
    int run = sb[t] - s;
#pragma unroll
    for (int i = 0; i < 4; i++) {
        int idx = base + i;
        if (idx < NN) off[idx] = run;
        run += v[i];
    }
    if (t == 255) g_blk[y][blockIdx.x] = sb[255];
}

__global__ void scan_mid() {
    int y = blockIdx.y;
    int* off = y ? g_off_b : g_off_a;
    __shared__ int sb[64];
    int t = threadIdx.x;
    int v = (t < 49) ? g_blk[y][t] : 0;
    sb[t] = v;
    __syncthreads();
    for (int d = 1; d < 64; d <<= 1) {
        int x = (t >= d) ? sb[t - d] : 0;
        __syncthreads();
        sb[t] += x;
        __syncthreads();
    }
    if (t < 49) g_blkoff[y][t] = sb[t] - v;
    if (t == 63) off[NN] = sb[63];
}

__global__ void scan_add() {
    int y = blockIdx.y;
    int* off = y ? g_off_b : g_off_a;
    int add = g_blkoff[y][blockIdx.x];
    int base = blockIdx.x * 1024 + threadIdx.x * 4;
#pragma unroll
    for (int i = 0; i < 4; i++) {
        int idx = base + i;
        if (idx < NN) off[idx] += add;
    }
}

__global__ void fill_kernel(const int* __restrict__ src_a, const int* __restrict__ dst_a,
                            const int* __restrict__ src_b, const int* __restrict__ dst_b) {
    int e = blockIdx.x * blockDim.x + threadIdx.x;
    if (e < EE) {
        int da = dst_a[e];
        int pa = g_off_a[da] + atomicAdd(&g_cur_a[da], 1);
        g_csr_a[pa] = src_a[e];
        int db = dst_b[e];
        int pb = g_off_b[db] + atomicAdd(&g_cur_b[db], 1);
        g_csr_b[pb] = src_b[e];
    }
}

// ---------------- input conversion fp32 -> packed ----------------
__global__ void conv_kernel(const float* __restrict__ xs, const float* __restrict__ xt) {
    int i = blockIdx.x * 256 + threadIdx.x;
    int base = i * 4;
    if (base >= TOT) return;
    const float* src = blockIdx.y ? xt : xs;
    unsigned* dst = blockIdx.y ? g_pxt : g_pxs;
    float4 v = *(const float4*)(src + base);
    uint4 o;
    o.x = pack_split(v.x); o.y = pack_split(v.y);
    o.z = pack_split(v.z); o.w = pack_split(v.w);
    *(uint4*)(dst + base) = o;
}

// ---------------- segment mean over packed activations (dual via blockIdx.y) ----------------
__global__ void segmean2_kernel(const unsigned* __restrict__ x0, const int* __restrict__ off0,
                                const int* __restrict__ csr0, unsigned* __restrict__ out0,
                                const unsigned* __restrict__ x1, const int* __restrict__ off1,
                                const int* __restrict__ csr1, unsigned* __restrict__ out1) {
    int y = blockIdx.y;
    const unsigned* x = y ? x1 : x0;
    const int* off = y ? off1 : off0;
    const int* csr = y ? csr1 : csr0;
    unsigned* out = y ? out1 : out0;
    int r = blockIdx.x;
    int t = threadIdx.x;  // 0..63, 4 elements each
    int s0 = off[r], s1 = off[r + 1];
    float a0 = 0.f, a1 = 0.f, a2 = 0.f, a3 = 0.f;
    for (int e = s0; e < s1; e++) {
        int src = csr[e];
        uint4 p = __ldg((const uint4*)(x + (size_t)src * DD) + t);
        a0 += unpack_val(p.x); a1 += unpack_val(p.y);
        a2 += unpack_val(p.z); a3 += unpack_val(p.w);
    }
    int cnt = s1 - s0;
    float inv = 1.0f / (float)(cnt > 0 ? cnt : 1);
    uint4 o;
    o.x = pack_split(a0 * inv); o.y = pack_split(a1 * inv);
    o.z = pack_split(a2 * inv); o.w = pack_split(a3 * inv);
    ((uint4*)(out + (size_t)r * DD))[t] = o;
}

// ---------------- weight prep: transpose + fp32 -> fp16 (hi only) ----------------
__global__ void wprep_kernel(const float* __restrict__ Wl_st, const float* __restrict__ Wr_st,
                             const float* __restrict__ Wl_ts, const float* __restrict__ Wr_ts) {
    int m = blockIdx.y;           // 0..7
    int layer = m >> 2, t = m & 3;
    const float* base = (t == 0) ? Wl_st : (t == 1) ? Wr_st : (t == 2) ? Wl_ts : Wr_ts;
    const float* W = base + layer * 65536;
    int idx = blockIdx.x * 256 + threadIdx.x;
    int n = idx >> 8, k = idx & 255;
    g_wfh[m * 65536 + idx] = __float2half_rn(W[k * 256 + n]);
}

// ---------------- mma.sync fp16-split fused dual-GEMM + bias + leaky + dropout ----------------
// x = xh + xl (fp16 each); result = (xh + xl) @ Wh  (W-low dropped, rel err ~1.4e-4)
// 3-stage smem rotation (Ah, Al, Bh per stage), ONE __syncthreads per k-chunk, 2 CTAs/SM.
#define ASTRIDE 20
#define ST_U32 7680           // 3 tiles * 128 rows * 20 u32 (one stage)
#define OFF_AH 0
#define OFF_AL 2560
#define OFF_BH 5120
#define SMEM_GEMM (3 * ST_U32 * 4)   // 92160 B -> 2 CTAs/SM

#define LDSM4(r0, r1, r2, r3, addr) \
    asm volatile("ldmatrix.sync.aligned.m8n8.x4.shared.b16 {%0,%1,%2,%3}, [%4];" \
                 : "=r"(r0), "=r"(r1), "=r"(r2), "=r"(r3) : "r"(addr))

#define MMA16816(c, a, b0, b1) \
    asm volatile("mma.sync.aligned.m16n8k16.row.col.f32.f16.f16.f32 " \
                 "{%0,%1,%2,%3}, {%4,%5,%6,%7}, {%8,%9}, {%0,%1,%2,%3};" \
                 : "+f"((c)[0]), "+f"((c)[1]), "+f"((c)[2]), "+f"((c)[3]) \
                 : "r"((a)[0]), "r"((a)[1]), "r"((a)[2]), "r"((a)[3]), "r"(b0), "r"(b1))

struct GArgs {
    const unsigned *A1, *A2;
    const __half *W1h, *W2h;
    const float* bias;
    unsigned* outC;
    unsigned dk0, dk1;
};

__global__ void __launch_bounds__(256, 2) gemm_mma(GArgs ga, GArgs gb, int M) {
    extern __shared__ uint32_t sm[];
    const GArgs g = blockIdx.z ? gb : ga;
    const unsigned* __restrict__ A1 = g.A1;
    const unsigned* __restrict__ A2 = g.A2;
    const __half* __restrict__ W1h = g.W1h;
    const __half* __restrict__ W2h = g.W2h;
    const float* __restrict__ bias = g.bias;
    unsigned* __restrict__ C = g.outC;
    const unsigned dk0 = g.dk0, dk1 = g.dk1;

    const int tid = threadIdx.x;
    const int lane = tid & 31, wid = tid >> 5;
    const int warpM = wid & 3, warpN = wid >> 2;      // 4 x 2 warps
    const int rowBase = blockIdx.y * MTILE;
    const int colBase = blockIdx.x * 128;
    const uint32_t smaddr = smem_u32(sm);

    float acc[2][8][4];
#pragma unroll
    for (int i = 0; i < 2; i++)
#pragma unroll
        for (int j = 0; j < 8; j++)
#pragma unroll
            for (int q = 0; q < 4; q++) acc[i][j][q] = 0.f;

    uint4 aReg[4];
    uint4 bReg[2];

    uint32_t aAddr[2][2], bAddr[4][2];
#pragma unroll
    for (int mt = 0; mt < 2; mt++)
#pragma unroll
        for (int ks = 0; ks < 2; ks++) {
            int row = warpM * 32 + mt * 16 + (lane & 15);
            int kOff = ks * 16 + (lane >> 4) * 8;
            aAddr[mt][ks] = smaddr + (uint32_t)(OFF_AH + row * ASTRIDE + (kOff >> 1)) * 4;
        }
#pragma unroll
    for (int np = 0; np < 4; np++)
#pragma unroll
        for (int ks = 0; ks < 2; ks++) {
            int n = warpN * 64 + np * 16 + (lane & 7) + (lane >> 4) * 8;
            int kOff = ks * 16 + ((lane >> 3) & 1) * 8;
            bAddr[np][ks] = smaddr + (uint32_t)(OFF_BH + n * ASTRIDE + (kOff >> 1)) * 4;
        }

#define GLOAD(c) do { \
        int mat_ = (c) >> 3; int kb_ = ((c) & 7) * 32; \
        const unsigned* A_ = mat_ ? A2 : A1; \
        const __half* Bh_ = mat_ ? W2h : W1h; \
        _Pragma("unroll") \
        for (int j = 0; j < 4; j++) { \
            int idx = tid + j * 256; \
            int r = idx >> 3, kq = (idx & 7) * 4; \
            int gr = rowBase + r; \
            aReg[j] = (gr < M) ? *(const uint4*)(A_ + (size_t)gr * 256 + kb_ + kq) \
                               : make_uint4(0u, 0u, 0u, 0u); \
        } \
        _Pragma("unroll") \
        for (int j = 0; j < 2; j++) { \
            int idx = tid + j * 256; \
            int n = idx >> 2, ko = (idx & 3) * 8; \
            bReg[j] = *(const uint4*)(Bh_ + (size_t)(colBase + n) * 256 + kb_ + ko); \
        } \
    } while (0)

#define SSTORE(st) do { \
        uint32_t* base_ = sm + (st) * ST_U32; \
        _Pragma("unroll") \
        for (int j = 0; j < 4; j++) { \
            int idx = tid + j * 256; \
            int r = idx >> 3, kq = (idx & 7) * 4; \
            uint4 p = aReg[j]; \
            uint32_t ah01 = __byte_perm(p.x, p.y, 0x5410); \
            uint32_t al01 = __byte_perm(p.x, p.y, 0x7632); \
            uint32_t ah23 = __byte_perm(p.z, p.w, 0x5410); \
            uint32_t al23 = __byte_perm(p.z, p.w, 0x7632); \
            uint32_t off = (uint32_t)(r * ASTRIDE + (kq >> 1)); \
            base_[OFF_AH + off]     = ah01; \
            base_[OFF_AH + off + 1] = ah23; \
            base_[OFF_AL + off]     = al01; \
            base_[OFF_AL + off + 1] = al23; \
        } \
        _Pragma("unroll") \
        for (int j = 0; j < 2; j++) { \
            int idx = tid + j * 256; \
            int n = idx >> 2, ko = (idx & 3) * 8; \
            uint32_t off = (uint32_t)(n * ASTRIDE + (ko >> 1)); \
            *(uint4*)(base_ + OFF_BH + off) = bReg[j]; \
        } \
    } while (0)

    GLOAD(0);
    SSTORE(0);
    __syncthreads();

#pragma unroll 1
    for (int c = 0; c < 16; c++) {
        if (c < 15) GLOAD(c + 1);
        const uint32_t stOff = (uint32_t)(c % 3) * (ST_U32 * 4);
#pragma unroll
        for (int ks = 0; ks < 2; ks++) {
            uint32_t ah[2][4], al[2][4], bh[4][4];
#pragma unroll
            for (int mt = 0; mt < 2; mt++) {
                uint32_t ad = aAddr[mt][ks] + stOff;
                LDSM4(ah[mt][0], ah[mt][1], ah[mt][2], ah[mt][3], ad);
                LDSM4(al[mt][0], al[mt][1], al[mt][2], al[mt][3], ad + (OFF_AL - OFF_AH) * 4);
            }
#pragma unroll
            for (int np = 0; np < 4; np++) {
                uint32_t bd = bAddr[np][ks] + stOff;
                LDSM4(bh[np][0], bh[np][1], bh[np][2], bh[np][3], bd);
            }
#pragma unroll
            for (int mt = 0; mt < 2; mt++)
#pragma unroll
                for (int nt = 0; nt < 8; nt++) {
                    int grp = nt >> 1, pr = (nt & 1) * 2;
                    MMA16816(acc[mt][nt], ah[mt], bh[grp][pr], bh[grp][pr + 1]);
                    MMA16816(acc[mt][nt], al[mt], bh[grp][pr], bh[grp][pr + 1]);
                }
        }
        if (c < 15) SSTORE((c + 1) % 3);
        __syncthreads();
    }

    // epilogue: bias + leaky-relu + dropout + pack, store packed u32
    const float sc = 1.0f / 0.9f;
#pragma unroll
    for (int mt = 0; mt < 2; mt++)
#pragma unroll
        for (int nt = 0; nt < 8; nt++) {
            int col = colBase + warpN * 64 + nt * 8 + (lane & 3) * 2;
            float2 bv = *(const float2*)(bias + col);
#pragma unroll
            for (int half = 0; half < 2; half++) {
                int r = rowBase + warpM * 32 + mt * 16 + (lane >> 2) + half * 8;
                if (r >= M) continue;
                float v0 = acc[mt][nt][half * 2 + 0] + bv.x;
                float v1 = acc[mt][nt][half * 2 + 1] + bv.y;
                v0 = v0 >= 0.f ? v0 : 0.01f * v0;
                v1 = v1 >= 0.f ? v1 : 0.01f * v1;
                unsigned i0 = (unsigned)r * 256u + (unsigned)col;
                unsigned q0 = jax_bits32(dk0, dk1, i0);
                unsigned q1 = jax_bits32(dk0, dk1, i0 + 1u);
                float u0 = __uint_as_float((q0 >> 9) | 0x3f800000u) - 1.0f;
                float u1 = __uint_as_float((q1 >> 9) | 0x3f800000u) - 1.0f;
                v0 = (u0 < 0.9f) ? v0 * sc : 0.0f;
                v1 = (u1 < 0.9f) ? v1 * sc : 0.0f;
                *(uint2*)(C + (size_t)r * 256 + col) = make_uint2(pack_split(v0), pack_split(v1));
            }
        }
}

// ---------------- output GEMM: out[50000x16] = unpack(x) @ Wout + bout ----------------
__global__ void out_kernel(const unsigned* __restrict__ x, const float* __restrict__ W,
                           const float* __restrict__ b, float* __restrict__ out, int M) {
    __shared__ float Ws[256 * 16];
    __shared__ float Xs[16 * 256];
    int tid = threadIdx.x;
    int rowBase = blockIdx.x * 16;
    for (int i = tid; i < 256 * 16 / 4; i += 256)
        ((float4*)Ws)[i] = ((const float4*)W)[i];
    for (int i = tid; i < 16 * 64; i += 256) {
        int rr = i >> 6, c4 = i & 63;
        int gr = rowBase + rr;
        float4 v = make_float4(0.f, 0.f, 0.f, 0.f);
        if (gr < M) {
            uint4 p = ((const uint4*)(x + (size_t)gr * 256))[c4];
            v.x = unpack_val(p.x); v.y = unpack_val(p.y);
            v.z = unpack_val(p.z); v.w = unpack_val(p.w);
        }
        ((float4*)(Xs + rr * 256))[c4] = v;
    }
    __syncthreads();
    int rr = tid >> 4, cc = tid & 15;
    float acc = 0.f;
#pragma unroll 8
    for (int k = 0; k < 256; k++) acc += Xs[rr * 256 + k] * Ws[k * 16 + cc];
    int gr = rowBase + rr;
    if (gr < M) out[(size_t)gr * 16 + cc] = acc + b[cc];
}

// ---------------- host ----------------
extern "C" void kernel_launch(void* const* d_in, const int* in_sizes, int n_in,
                              void* d_out, int out_size) {
    const float* x_source = (const float*)d_in[0];
    const float* x_target = (const float*)d_in[1];
    const int* ei_st = (const int*)d_in[2];
    const int* ei_ts = (const int*)d_in[3];
    const float* Wl_st = (const float*)d_in[4];
    const float* Wr_st = (const float*)d_in[5];
    const float* b_st = (const float*)d_in[6];
    const float* Wl_ts = (const float*)d_in[7];
    const float* Wr_ts = (const float*)d_in[8];
    const float* b_ts = (const float*)d_in[9];
    const float* Wout = (const float*)d_in[10];
    const float* bout = (const float*)d_in[11];
    float* out = (float*)d_out;

    void* p;
    unsigned *pxs, *pxt, *pma, *pmb, *pxt0, *pxs0, *pxs1;
    __half* wfh;
    cudaGetSymbolAddress(&p, g_pxs);  pxs = (unsigned*)p;
    cudaGetSymbolAddress(&p, g_pxt);  pxt = (unsigned*)p;
    cudaGetSymbolAddress(&p, g_pma);  pma = (unsigned*)p;
    cudaGetSymbolAddress(&p, g_pmb);  pmb = (unsigned*)p;
    cudaGetSymbolAddress(&p, g_pxt0); pxt0 = (unsigned*)p;
    cudaGetSymbolAddress(&p, g_pxs0); pxs0 = (unsigned*)p;
    cudaGetSymbolAddress(&p, g_pxs1); pxs1 = (unsigned*)p;
    cudaGetSymbolAddress(&p, g_wfh);  wfh = (__half*)p;
    int *off_a, *off_b, *csr_a, *csr_b;
    cudaGetSymbolAddress(&p, g_off_a); off_a = (int*)p;
    cudaGetSymbolAddress(&p, g_off_b); off_b = (int*)p;
    cudaGetSymbolAddress(&p, g_csr_a); csr_a = (int*)p;
    cudaGetSymbolAddress(&p, g_csr_b); csr_b = (int*)p;

    cudaFuncSetAttribute(gemm_mma, cudaFuncAttributeMaxDynamicSharedMemorySize, SMEM_GEMM);

    const int* src_st = ei_st;
    const int* dst_st = ei_st + EE;
    const int* src_ts = ei_ts;
    const int* dst_ts = ei_ts + EE;

    // dropout keys: fold_in(key(42)=(0,42), d); d=0 -> xs0, d=1 -> xt0, d=2 -> xs1
    unsigned dkeys[3][2];
    for (int d = 0; d < 3; d++)
        tf2x32(0u, 42u, 0u, (unsigned)d, dkeys[d][0], dkeys[d][1]);

    wprep_kernel<<<dim3(256, 8), 256>>>(Wl_st, Wr_st, Wl_ts, Wr_ts);
    conv_kernel<<<dim3(12500, 2), 256>>>(x_source, x_target);
    zero_kernel<<<(NN + 255) / 256, 256>>>();
    count_kernel<<<(EE + 255) / 256, 256>>>(dst_st, dst_ts);
    scan_pre<<<dim3(49, 2), 256>>>();
    scan_mid<<<dim3(1, 2), 64>>>();
    scan_add<<<dim3(49, 2), 256>>>();
    fill_kernel<<<(EE + 255) / 256, 256>>>(src_st, dst_st, src_ts, dst_ts);

    const int M64K = 65536;

    // ---- layer 0: both segmeans in one launch, both gemms in one launch ----
    segmean2_kernel<<<dim3(NN, 2), 64>>>(pxs, off_a, csr_a, pma,
                                         pxt, off_b, csr_b, pmb);
    GArgs gA, gB;
    // z=0: new_t = m_t@Wl_st + x_t@Wr_st + b_st -> pxt0 (key d=1)
    gA.A1 = pma; gA.A2 = pxt;
    gA.W1h = wfh + 0 * M64K; gA.W2h = wfh + 1 * M64K;
    gA.bias = b_st; gA.outC = pxt0; gA.dk0 = dkeys[1][0]; gA.dk1 = dkeys[1][1];
    // z=1: new_s = m_s@Wl_ts + x_s@Wr_ts + b_ts -> pxs0 (key d=0)
    gB.A1 = pmb; gB.A2 = pxs;
    gB.W1h = wfh + 2 * M64K; gB.W2h = wfh + 3 * M64K;
    gB.bias = b_ts; gB.outC = pxs0; gB.dk0 = dkeys[0][0]; gB.dk1 = dkeys[0][1];
    gemm_mma<<<dim3(2, NBLKY, 2), 256, SMEM_GEMM>>>(gA, gB, NN);

    // ---- layer 1 (target branch is dead) ----
    segmean2_kernel<<<dim3(NN, 1), 64>>>(pxt0, off_b, csr_b, pma,
                                         pxt0, off_b, csr_b, pma);
    GArgs gC;
    gC.A1 = pma; gC.A2 = pxs0;
    gC.W1h = wfh + 6 * M64K; gC.W2h = wfh + 7 * M64K;
    gC.bias = b_ts + 256; gC.outC = pxs1; gC.dk0 = dkeys[2][0]; gC.dk1 = dkeys[2][1];
    gemm_mma<<<dim3(2, NBLKY, 1), 256, SMEM_GEMM>>>(gC, gC, NN);

    // ---- output projection ----
    out_kernel<<<(NN + 15) / 16, 256>>>(pxs1, Wout, bout, out, NN);
}

// round 10
// speedup vs baseline: 1.4013x; 1.0023x over previous
#include <cuda_runtime.h>
#include <cuda_fp16.h>
#include <cstdint>

#define NN 50000
#define DD 256
#define EE 320000
#define TOT (NN * DD)
#define MTILE 128
#define NBLKY ((NN + MTILE - 1) / MTILE)   // 391

// ---------------- scratch (static __device__ — no allocation allowed) ----------------
__device__ int g_cnt_a[NN], g_cnt_b[NN], g_cur_a[NN], g_cur_b[NN];
__device__ int g_off_a[NN + 1], g_off_b[NN + 1];
__device__ int g_csr_a[EE], g_csr_b[EE];
__device__ int g_blk[2][49], g_blkoff[2][49];
// packed u32 (fp16 hi | fp16 lo<<16) split activations: value = hi + lo (~2^-21 exact)
__device__ unsigned g_pxs[TOT], g_pxt[TOT];
__device__ unsigned g_pma[TOT], g_pmb[TOT];
__device__ unsigned g_pxt0[TOT], g_pxs0[TOT];
// pre-transposed fp16 weights (hi only — W-low term dropped): 8 matrices [n=256][k=256]
__device__ __half g_wfh[8 * 65536];

// ---------------- threefry-2x32 (exactly JAX's) ----------------
__host__ __device__ __forceinline__ unsigned rotl32(unsigned x, int d) {
    return (x << d) | (x >> (32 - d));
}

__host__ __device__ __forceinline__ void tf2x32(unsigned k0, unsigned k1,
                                                unsigned x0, unsigned x1,
                                                unsigned& o0, unsigned& o1) {
    unsigned ks2 = k0 ^ k1 ^ 0x1BD11BDAu;
    x0 += k0; x1 += k1;
#define TF_ROUND(r) { x0 += x1; x1 = rotl32(x1, r); x1 ^= x0; }
    TF_ROUND(13) TF_ROUND(15) TF_ROUND(26) TF_ROUND(6)
    x0 += k1;  x1 += ks2 + 1u;
    TF_ROUND(17) TF_ROUND(29) TF_ROUND(16) TF_ROUND(24)
    x0 += ks2; x1 += k0 + 2u;
    TF_ROUND(13) TF_ROUND(15) TF_ROUND(26) TF_ROUND(6)
    x0 += k0;  x1 += k1 + 3u;
    TF_ROUND(17) TF_ROUND(29) TF_ROUND(16) TF_ROUND(24)
    x0 += k1;  x1 += ks2 + 4u;
    TF_ROUND(13) TF_ROUND(15) TF_ROUND(26) TF_ROUND(6)
    x0 += ks2; x1 += k0 + 5u;
#undef TF_ROUND
    o0 = x0; o1 = x1;
}

__device__ __forceinline__ unsigned jax_bits32(unsigned k0, unsigned k1, unsigned i) {
    unsigned o0, o1;
    tf2x32(k0, k1, 0u, i, o0, o1);
    return o0 ^ o1;
}

__device__ __forceinline__ uint32_t smem_u32(const void* p) {
    uint32_t a;
    asm("{ .reg .u64 t; cvta.to.shared.u64 t, %1; cvt.u32.u64 %0, t; }" : "=r"(a) : "l"(p));
    return a;
}

// ---------------- packed fp16-split helpers ----------------
__device__ __forceinline__ unsigned pack_split(float v) {
    __half h = __float2half_rn(v);
    float hf = __half2float(h);
    __half l = __float2half_rn(v - hf);
    return (unsigned)__half_as_ushort(h) | ((unsigned)__half_as_ushort(l) << 16);
}

__device__ __forceinline__ float unpack_val(unsigned p) {
    __half h = __ushort_as_half((unsigned short)(p & 0xFFFFu));
    __half l = __ushort_as_half((unsigned short)(p >> 16));
    return __half2float(h) + __half2float(l);
}

// ---------------- CSR build ----------------
__global__ void zero_kernel() {
    int i = blockIdx.x * blockDim.x + threadIdx.x;
    if (i < NN) { g_cnt_a[i] = 0; g_cnt_b[i] = 0; g_cur_a[i] = 0; g_cur_b[i] = 0; }
}

__global__ void count_kernel(const int* __restrict__ dst_a, const int* __restrict__ dst_b) {
    int e = blockIdx.x * blockDim.x + threadIdx.x;
    if (e < EE) {
        atomicAdd(&g_cnt_a[dst_a[e]], 1);
        atomicAdd(&g_cnt_b[dst_b[e]], 1);
    }
}

__global__ void scan_pre() {
    int y = blockIdx.y;
    const int* cnt = y ? g_cnt_b : g_cnt_a;
    int* off = y ? g_off_b : g_off_a;
    __shared__ int sb[256];
    int t = threadIdx.x;
    int base = blockIdx.x * 1024 + t * 4;
    int v[4]; int s = 0;
#pragma unroll
    for (int i = 0; i < 4; i++) {
        int idx = base + i;
        v[i] = (idx < NN) ? cnt[idx] : 0;
        s += v[i];
    }
    sb[t] = s;
    __syncthreads();
    for (int d = 1; d < 256; d <<= 1) {
        int x = (t >= d) ? sb[t - d] : 0;
        __syncthreads();
        sb[t] += x;
        __syncthreads();
    }
    int run = sb[t] - s;
#pragma unroll
    for (int i = 0; i < 4; i++) {
        int idx = base + i;
        if (idx < NN) off[idx] = run;
        run += v[i];
    }
    if (t == 255) g_blk[y][blockIdx.x] = sb[255];
}

__global__ void scan_mid() {
    int y = blockIdx.y;
    int* off = y ? g_off_b : g_off_a;
    __shared__ int sb[64];
    int t = threadIdx.x;
    int v = (t < 49) ? g_blk[y][t] : 0;
    sb[t] = v;
    __syncthreads();
    for (int d = 1; d < 64; d <<= 1) {
        int x = (t >= d) ? sb[t - d] : 0;
        __syncthreads();
        sb[t] += x;
        __syncthreads();
    }
    if (t < 49) g_blkoff[y][t] = sb[t] - v;
    if (t == 63) off[NN] = sb[63];
}

__global__ void scan_add() {
    int y = blockIdx.y;
    int* off = y ? g_off_b : g_off_a;
    int add = g_blkoff[y][blockIdx.x];
    int base = blockIdx.x * 1024 + threadIdx.x * 4;
#pragma unroll
    for (int i = 0; i < 4; i++) {
        int idx = base + i;
        if (idx < NN) off[idx] += add;
    }
}

__global__ void fill_kernel(const int* __restrict__ src_a, const int* __restrict__ dst_a,
                            const int* __restrict__ src_b, const int* __restrict__ dst_b) {
    int e = blockIdx.x * blockDim.x + threadIdx.x;
    if (e < EE) {
        int da = dst_a[e];
        int pa = g_off_a[da] + atomicAdd(&g_cur_a[da], 1);
        g_csr_a[pa] = src_a[e];
        int db = dst_b[e];
        int pb = g_off_b[db] + atomicAdd(&g_cur_b[db], 1);
        g_csr_b[pb] = src_b[e];
    }
}

// ---------------- init out to broadcast bias ----------------
__global__ void initout_kernel(const float* __restrict__ bout, float* __restrict__ out) {
    int i = blockIdx.x * 256 + threadIdx.x;   // float4 index
    if (i < (NN * 16) / 4) {
        int j4 = (i & 3) * 4;
        ((float4*)out)[i] = make_float4(bout[j4], bout[j4 + 1], bout[j4 + 2], bout[j4 + 3]);
    }
}

// ---------------- input conversion fp32 -> packed ----------------
__global__ void conv_kernel(const float* __restrict__ xs, const float* __restrict__ xt) {
    int i = blockIdx.x * 256 + threadIdx.x;
    int base = i * 4;
    if (base >= TOT) return;
    const float* src = blockIdx.y ? xt : xs;
    unsigned* dst = blockIdx.y ? g_pxt : g_pxs;
    float4 v = *(const float4*)(src + base);
    uint4 o;
    o.x = pack_split(v.x); o.y = pack_split(v.y);
    o.z = pack_split(v.z); o.w = pack_split(v.w);
    *(uint4*)(dst + base) = o;
}

// ---------------- segment mean (2-edge unrolled, dual via blockIdx.y) ----------------
__global__ void segmean2_kernel(const unsigned* __restrict__ x0, const int* __restrict__ off0,
                                const int* __restrict__ csr0, unsigned* __restrict__ out0,
                                const unsigned* __restrict__ x1, const int* __restrict__ off1,
                                const int* __restrict__ csr1, unsigned* __restrict__ out1) {
    int y = blockIdx.y;
    const unsigned* x = y ? x1 : x0;
    const int* off = y ? off1 : off0;
    const int* csr = y ? csr1 : csr0;
    unsigned* out = y ? out1 : out0;
    int r = blockIdx.x;
    int t = threadIdx.x;  // 0..63, 4 elements each
    int s0 = off[r], s1 = off[r + 1];
    float a0 = 0.f, a1 = 0.f, a2 = 0.f, a3 = 0.f;
    float b0 = 0.f, b1 = 0.f, b2 = 0.f, b3 = 0.f;
    int e = s0;
    for (; e + 2 <= s1; e += 2) {
        int sA = csr[e], sB = csr[e + 1];
        uint4 p = __ldg((const uint4*)(x + (size_t)sA * DD) + t);
        uint4 q = __ldg((const uint4*)(x + (size_t)sB * DD) + t);
        a0 += unpack_val(p.x); a1 += unpack_val(p.y);
        a2 += unpack_val(p.z); a3 += unpack_val(p.w);
        b0 += unpack_val(q.x); b1 += unpack_val(q.y);
        b2 += unpack_val(q.z); b3 += unpack_val(q.w);
    }
    if (e < s1) {
        int sA = csr[e];
        uint4 p = __ldg((const uint4*)(x + (size_t)sA * DD) + t);
        a0 += unpack_val(p.x); a1 += unpack_val(p.y);
        a2 += unpack_val(p.z); a3 += unpack_val(p.w);
    }
    a0 += b0; a1 += b1; a2 += b2; a3 += b3;
    int cnt = s1 - s0;
    float inv = 1.0f / (float)(cnt > 0 ? cnt : 1);
    uint4 o;
    o.x = pack_split(a0 * inv); o.y = pack_split(a1 * inv);
    o.z = pack_split(a2 * inv); o.w = pack_split(a3 * inv);
    ((uint4*)(out + (size_t)r * DD))[t] = o;
}

// ---------------- weight prep: transpose + fp32 -> fp16 (hi only) ----------------
__global__ void wprep_kernel(const float* __restrict__ Wl_st, const float* __restrict__ Wr_st,
                             const float* __restrict__ Wl_ts, const float* __restrict__ Wr_ts) {
    int m = blockIdx.y;           // 0..7
    int layer = m >> 2, t = m & 3;
    const float* base = (t == 0) ? Wl_st : (t == 1) ? Wr_st : (t == 2) ? Wl_ts : Wr_ts;
    const float* W = base + layer * 65536;
    int idx = blockIdx.x * 256 + threadIdx.x;
    int n = idx >> 8, k = idx & 255;
    g_wfh[m * 65536 + idx] = __float2half_rn(W[k * 256 + n]);
}

// ---------------- mma.sync fp16-split fused dual-GEMM + bias + leaky + dropout ----------------
// FUSE=true additionally computes out[r][0..15] += dropout_result_row @ Wout (no C store).
#define ASTRIDE 20
#define ST_U32 7680           // 3 tiles * 128 rows * 20 u32 (one stage)
#define OFF_AH 0
#define OFF_AL 2560
#define OFF_BH 5120
#define WS_OFF (3 * ST_U32)   // fp32 Wout slice [128][16] (FUSE only)
#define VSTRIDE 132           // v-tile row stride in u32 (128 + 4 pad)
#define SMEM_GEMM   (3 * ST_U32 * 4)            // 92160 B
#define SMEM_GEMM_F (3 * ST_U32 * 4 + 8192)     // + 2048 fp32 Wout slice

#define LDSM4(r0, r1, r2, r3, addr) \
    asm volatile("ldmatrix.sync.aligned.m8n8.x4.shared.b16 {%0,%1,%2,%3}, [%4];" \
                 : "=r"(r0), "=r"(r1), "=r"(r2), "=r"(r3) : "r"(addr))

#define MMA16816(c, a, b0, b1) \
    asm volatile("mma.sync.aligned.m16n8k16.row.col.f32.f16.f16.f32 " \
                 "{%0,%1,%2,%3}, {%4,%5,%6,%7}, {%8,%9}, {%0,%1,%2,%3};" \
                 : "+f"((c)[0]), "+f"((c)[1]), "+f"((c)[2]), "+f"((c)[3]) \
                 : "r"((a)[0]), "r"((a)[1]), "r"((a)[2]), "r"((a)[3]), "r"(b0), "r"(b1))

struct GArgs {
    const unsigned *A1, *A2;
    const __half *W1h, *W2h;
    const float* bias;
    unsigned* outC;
    const float* Wproj;   // FUSE: Wout [256][16]
    float* outF;          // FUSE: out [M][16]
    unsigned dk0, dk1;
};

template <bool FUSE>
__global__ void __launch_bounds__(256, 2) gemm_mma(GArgs ga, GArgs gb, int M) {
    extern __shared__ uint32_t sm[];
    const GArgs g = blockIdx.z ? gb : ga;
    const unsigned* __restrict__ A1 = g.A1;
    const unsigned* __restrict__ A2 = g.A2;
    const __half* __restrict__ W1h = g.W1h;
    const __half* __restrict__ W2h = g.W2h;
    const float* __restrict__ bias = g.bias;
    unsigned* __restrict__ C = g.outC;
    const unsigned dk0 = g.dk0, dk1 = g.dk1;

    const int tid = threadIdx.x;
    const int lane = tid & 31, wid = tid >> 5;
    const int warpM = wid & 3, warpN = wid >> 2;      // 4 x 2 warps
    const int rowBase = blockIdx.y * MTILE;
    const int colBase = blockIdx.x * 128;
    const uint32_t smaddr = smem_u32(sm);

    if (FUSE) {
        // load Wout slice for this CTA's 128 cols: [128][16] fp32
        float* WsS = (float*)(sm + WS_OFF);
        const uint4* src = (const uint4*)(g.Wproj + (size_t)colBase * 16);
#pragma unroll
        for (int i = 0; i < 2; i++)
            ((uint4*)WsS)[tid + i * 256] = src[tid + i * 256];
    }

    float acc[2][8][4];
#pragma unroll
    for (int i = 0; i < 2; i++)
#pragma unroll
        for (int j = 0; j < 8; j++)
#pragma unroll
            for (int q = 0; q < 4; q++) acc[i][j][q] = 0.f;

    uint4 aReg[4];
    uint4 bReg[2];

    uint32_t aAddr[2][2], bAddr[4][2];
#pragma unroll
    for (int mt = 0; mt < 2; mt++)
#pragma unroll
        for (int ks = 0; ks < 2; ks++) {
            int row = warpM * 32 + mt * 16 + (lane & 15);
            int kOff = ks * 16 + (lane >> 4) * 8;
            aAddr[mt][ks] = smaddr + (uint32_t)(OFF_AH + row * ASTRIDE + (kOff >> 1)) * 4;
        }
#pragma unroll
    for (int np = 0; np < 4; np++)
#pragma unroll
        for (int ks = 0; ks < 2; ks++) {
            int n = warpN * 64 + np * 16 + (lane & 7) + (lane >> 4) * 8;
            int kOff = ks * 16 + ((lane >> 3) & 1) * 8;
            bAddr[np][ks] = smaddr + (uint32_t)(OFF_BH + n * ASTRIDE + (kOff >> 1)) * 4;
        }

#define GLOAD(c) do { \
        int mat_ = (c) >> 3; int kb_ = ((c) & 7) * 32; \
        const unsigned* A_ = mat_ ? A2 : A1; \
        const __half* Bh_ = mat_ ? W2h : W1h; \
        _Pragma("unroll") \
        for (int j = 0; j < 4; j++) { \
            int idx = tid + j * 256; \
            int r = idx >> 3, kq = (idx & 7) * 4; \
            int gr = rowBase + r; \
            aReg[j] = (gr < M) ? *(const uint4*)(A_ + (size_t)gr * 256 + kb_ + kq) \
                               : make_uint4(0u, 0u, 0u, 0u); \
        } \
        _Pragma("unroll") \
        for (int j = 0; j < 2; j++) { \
            int idx = tid + j * 256; \
            int n = idx >> 2, ko = (idx & 3) * 8; \
            bReg[j] = *(const uint4*)(Bh_ + (size_t)(colBase + n) * 256 + kb_ + ko); \
        } \
    } while (0)

#define SSTORE(st) do { \
        uint32_t* base_ = sm + (st) * ST_U32; \
        _Pragma("unroll") \
        for (int j = 0; j < 4; j++) { \
            int idx = tid + j * 256; \
            int r = idx >> 3, kq = (idx & 7) * 4; \
            uint4 p = aReg[j]; \
            uint32_t ah01 = __byte_perm(p.x, p.y, 0x5410); \
            uint32_t al01 = __byte_perm(p.x, p.y, 0x7632); \
            uint32_t ah23 = __byte_perm(p.z, p.w, 0x5410); \
            uint32_t al23 = __byte_perm(p.z, p.w, 0x7632); \
            uint32_t off = (uint32_t)(r * ASTRIDE + (kq >> 1)); \
            base_[OFF_AH + off]     = ah01; \
            base_[OFF_AH + off + 1] = ah23; \
            base_[OFF_AL + off]     = al01; \
            base_[OFF_AL + off + 1] = al23; \
        } \
        _Pragma("unroll") \
        for (int j = 0; j < 2; j++) { \
            int idx = tid + j * 256; \
            int n = idx >> 2, ko = (idx & 3) * 8; \
            uint32_t off = (uint32_t)(n * ASTRIDE + (ko >> 1)); \
            *(uint4*)(base_ + OFF_BH + off) = bReg[j]; \
        } \
    } while (0)

    GLOAD(0);
    SSTORE(0);
    __syncthreads();

#pragma unroll 1
    for (int c = 0; c < 16; c++) {
        if (c < 15) GLOAD(c + 1);
        const uint32_t stOff = (uint32_t)(c % 3) * (ST_U32 * 4);
#pragma unroll
        for (int ks = 0; ks < 2; ks++) {
            uint32_t ah[2][4], al[2][4], bh[4][4];
#pragma unroll
            for (int mt = 0; mt < 2; mt++) {
                uint32_t ad = aAddr[mt][ks] + stOff;
                LDSM4(ah[mt][0], ah[mt][1], ah[mt][2], ah[mt][3], ad);
                LDSM4(al[mt][0], al[mt][1], al[mt][2], al[mt][3], ad + (OFF_AL - OFF_AH) * 4);
            }
#pragma unroll
            for (int np = 0; np < 4; np++) {
                uint32_t bd = bAddr[np][ks] + stOff;
                LDSM4(bh[np][0], bh[np][1], bh[np][2], bh[np][3], bd);
            }
#pragma unroll
            for (int mt = 0; mt < 2; mt++)
#pragma unroll
                for (int nt = 0; nt < 8; nt++) {
                    int grp = nt >> 1, pr = (nt & 1) * 2;
                    MMA16816(acc[mt][nt], ah[mt], bh[grp][pr], bh[grp][pr + 1]);
                    MMA16816(acc[mt][nt], al[mt], bh[grp][pr], bh[grp][pr + 1]);
                }
        }
        if (c < 15) SSTORE((c + 1) % 3);
        __syncthreads();
    }

    // epilogue: bias + leaky-relu + dropout
    const float sc = 1.0f / 0.9f;
#pragma unroll
    for (int mt = 0; mt < 2; mt++)
#pragma unroll
        for (int nt = 0; nt < 8; nt++) {
            int colL = warpN * 64 + nt * 8 + (lane & 3) * 2;
            int col = colBase + colL;
            float2 bv = *(const float2*)(bias + col);
#pragma unroll
            for (int half = 0; half < 2; half++) {
                int rL = warpM * 32 + mt * 16 + (lane >> 2) + half * 8;
                int r = rowBase + rL;
                float v0 = acc[mt][nt][half * 2 + 0] + bv.x;
                float v1 = acc[mt][nt][half * 2 + 1] + bv.y;
                v0 = v0 >= 0.f ? v0 : 0.01f * v0;
                v1 = v1 >= 0.f ? v1 : 0.01f * v1;
                unsigned i0 = (unsigned)r * 256u + (unsigned)col;
                unsigned q0 = jax_bits32(dk0, dk1, i0);
                unsigned q1 = jax_bits32(dk0, dk1, i0 + 1u);
                float u0 = __uint_as_float((q0 >> 9) | 0x3f800000u) - 1.0f;
                float u1 = __uint_as_float((q1 >> 9) | 0x3f800000u) - 1.0f;
                v0 = (u0 < 0.9f) ? v0 * sc : 0.0f;
                v1 = (u1 < 0.9f) ? v1 * sc : 0.0f;
                if (FUSE) {
                    // stage packed v into smem tile (stage mem free after mainloop)
                    *(uint2*)(sm + rL * VSTRIDE + colL) =
                        make_uint2(pack_split(v0), pack_split(v1));
                } else {
                    if (r < M)
                        *(uint2*)(C + (size_t)r * 256 + col) =
                            make_uint2(pack_split(v0), pack_split(v1));
                }
            }
        }

    if (FUSE) {
        __syncthreads();
        // cooperative projection: out[r][0..15] += vrow(128 cols) @ WsS(128x16)
        const float* WsS = (const float*)(sm + WS_OFF);
        int rL = tid >> 1;                 // 0..127
        int jB = (tid & 1) * 8;
        int r = rowBase + rL;
        float pr[8];
#pragma unroll
        for (int j = 0; j < 8; j++) pr[j] = 0.f;
        const uint32_t* vrow = sm + rL * VSTRIDE;
#pragma unroll 4
        for (int k = 0; k < 128; k += 4) {
            uint4 pv = *(const uint4*)(vrow + k);
            float vv0 = unpack_val(pv.x), vv1 = unpack_val(pv.y);
            float vv2 = unpack_val(pv.z), vv3 = unpack_val(pv.w);
#pragma unroll
            for (int j = 0; j < 8; j++) {
                pr[j] += vv0 * WsS[(k + 0) * 16 + jB + j];
                pr[j] += vv1 * WsS[(k + 1) * 16 + jB + j];
                pr[j] += vv2 * WsS[(k + 2) * 16 + jB + j];
                pr[j] += vv3 * WsS[(k + 3) * 16 + jB + j];
            }
        }
        if (r < M) {
            float* o = g.outF + (size_t)r * 16 + jB;
#pragma unroll
            for (int j = 0; j < 8; j++) atomicAdd(o + j, pr[j]);
        }
    }
}

// ---------------- host ----------------
extern "C" void kernel_launch(void* const* d_in, const int* in_sizes, int n_in,
                              void* d_out, int out_size) {
    const float* x_source = (const float*)d_in[0];
    const float* x_target = (const float*)d_in[1];
    const int* ei_st = (const int*)d_in[2];
    const int* ei_ts = (const int*)d_in[3];
    const float* Wl_st = (const float*)d_in[4];
    const float* Wr_st = (const float*)d_in[5];
    const float* b_st = (const float*)d_in[6];
    const float* Wl_ts = (const float*)d_in[7];
    const float* Wr_ts = (const float*)d_in[8];
    const float* b_ts = (const float*)d_in[9];
    const float* Wout = (const float*)d_in[10];
    const float* bout = (const float*)d_in[11];
    float* out = (float*)d_out;

    void* p;
    unsigned *pxs, *pxt, *pma, *pmb, *pxt0, *pxs0;
    __half* wfh;
    cudaGetSymbolAddress(&p, g_pxs);  pxs = (unsigned*)p;
    cudaGetSymbolAddress(&p, g_pxt);  pxt = (unsigned*)p;
    cudaGetSymbolAddress(&p, g_pma);  pma = (unsigned*)p;
    cudaGetSymbolAddress(&p, g_pmb);  pmb = (unsigned*)p;
    cudaGetSymbolAddress(&p, g_pxt0); pxt0 = (unsigned*)p;
    cudaGetSymbolAddress(&p, g_pxs0); pxs0 = (unsigned*)p;
    cudaGetSymbolAddress(&p, g_wfh);  wfh = (__half*)p;
    int *off_a, *off_b, *csr_a, *csr_b;
    cudaGetSymbolAddress(&p, g_off_a); off_a = (int*)p;
    cudaGetSymbolAddress(&p, g_off_b); off_b = (int*)p;
    cudaGetSymbolAddress(&p, g_csr_a); csr_a = (int*)p;
    cudaGetSymbolAddress(&p, g_csr_b); csr_b = (int*)p;

    cudaFuncSetAttribute(gemm_mma<false>, cudaFuncAttributeMaxDynamicSharedMemorySize, SMEM_GEMM);
    cudaFuncSetAttribute(gemm_mma<true>, cudaFuncAttributeMaxDynamicSharedMemorySize, SMEM_GEMM_F);

    const int* src_st = ei_st;
    const int* dst_st = ei_st + EE;
    const int* src_ts = ei_ts;
    const int* dst_ts = ei_ts + EE;

    // dropout keys: fold_in(key(42)=(0,42), d); d=0 -> xs0, d=1 -> xt0, d=2 -> xs1
    unsigned dkeys[3][2];
    for (int d = 0; d < 3; d++)
        tf2x32(0u, 42u, 0u, (unsigned)d, dkeys[d][0], dkeys[d][1]);

    wprep_kernel<<<dim3(256, 8), 256>>>(Wl_st, Wr_st, Wl_ts, Wr_ts);
    conv_kernel<<<dim3(12500, 2), 256>>>(x_source, x_target);
    zero_kernel<<<(NN + 255) / 256, 256>>>();
    initout_kernel<<<(NN * 16 / 4 + 255) / 256, 256>>>(bout, out);
    count_kernel<<<(EE + 255) / 256, 256>>>(dst_st, dst_ts);
    scan_pre<<<dim3(49, 2), 256>>>();
    scan_mid<<<dim3(1, 2), 64>>>();
    scan_add<<<dim3(49, 2), 256>>>();
    fill_kernel<<<(EE + 255) / 256, 256>>>(src_st, dst_st, src_ts, dst_ts);

    const int M64K = 65536;

    // ---- layer 0: both segmeans in one launch, both gemms in one launch ----
    segmean2_kernel<<<dim3(NN, 2), 64>>>(pxs, off_a, csr_a, pma,
                                         pxt, off_b, csr_b, pmb);
    GArgs gA = {}, gB = {};
    // z=0: new_t = m_t@Wl_st + x_t@Wr_st + b_st -> pxt0 (key d=1)
    gA.A1 = pma; gA.A2 = pxt;
    gA.W1h = wfh + 0 * M64K; gA.W2h = wfh + 1 * M64K;
    gA.bias = b_st; gA.outC = pxt0; gA.dk0 = dkeys[1][0]; gA.dk1 = dkeys[1][1];
    // z=1: new_s = m_s@Wl_ts + x_s@Wr_ts + b_ts -> pxs0 (key d=0)
    gB.A1 = pmb; gB.A2 = pxs;
    gB.W1h = wfh + 2 * M64K; gB.W2h = wfh + 3 * M64K;
    gB.bias = b_ts; gB.outC = pxs0; gB.dk0 = dkeys[0][0]; gB.dk1 = dkeys[0][1];
    gemm_mma<false><<<dim3(2, NBLKY, 2), 256, SMEM_GEMM>>>(gA, gB, NN);

    // ---- layer 1 (target branch dead); projection fused into gemm epilogue ----
    segmean2_kernel<<<dim3(NN, 1), 64>>>(pxt0, off_b, csr_b, pma,
                                         pxt0, off_b, csr_b, pma);
    GArgs gC = {};
    gC.A1 = pma; gC.A2 = pxs0;
    gC.W1h = wfh + 6 * M64K; gC.W2h = wfh + 7 * M64K;
    gC.bias = b_ts + 256; gC.outC = nullptr;
    gC.Wproj = Wout; gC.outF = out;
    gC.dk0 = dkeys[2][0]; gC.dk1 = dkeys[2][1];
    gemm_mma<true><<<dim3(2, NBLKY, 1), 256, SMEM_GEMM_F>>>(gC, gC, NN);
}

// round 11
// speedup vs baseline: 1.9109x; 1.3636x over previous
#include <cuda_runtime.h>
#include <cuda_fp16.h>
#include <cstdint>

#define NN 50000
#define DD 256
#define EE 320000
#define TOT (NN * DD)
#define MTILE 128
#define NBLKY ((NN + MTILE - 1) / MTILE)   // 391

// ---------------- scratch (static __device__ — no allocation allowed) ----------------
__device__ int g_cnt_a[NN], g_cnt_b[NN], g_cur_a[NN], g_cur_b[NN];
__device__ int g_off_a[NN + 1], g_off_b[NN + 1];
__device__ int g_csr_a[EE], g_csr_b[EE];
__device__ int g_blk[2][49], g_blkoff[2][49];
// pure fp16 activations
__device__ __half g_pxs[TOT], g_pxt[TOT];
__device__ __half g_pma[TOT], g_pmb[TOT];
__device__ __half g_pxt0[TOT], g_pxs0[TOT];
// pre-transposed fp16 weights: 8 matrices [n=256][k=256]
__device__ __half g_wfh[8 * 65536];

// ---------------- threefry-2x32 (exactly JAX's) ----------------
__host__ __device__ __forceinline__ unsigned rotl32(unsigned x, int d) {
    return (x << d) | (x >> (32 - d));
}

__host__ __device__ __forceinline__ void tf2x32(unsigned k0, unsigned k1,
                                                unsigned x0, unsigned x1,
                                                unsigned& o0, unsigned& o1) {
    unsigned ks2 = k0 ^ k1 ^ 0x1BD11BDAu;
    x0 += k0; x1 += k1;
#define TF_ROUND(r) { x0 += x1; x1 = rotl32(x1, r); x1 ^= x0; }
    TF_ROUND(13) TF_ROUND(15) TF_ROUND(26) TF_ROUND(6)
    x0 += k1;  x1 += ks2 + 1u;
    TF_ROUND(17) TF_ROUND(29) TF_ROUND(16) TF_ROUND(24)
    x0 += ks2; x1 += k0 + 2u;
    TF_ROUND(13) TF_ROUND(15) TF_ROUND(26) TF_ROUND(6)
    x0 += k0;  x1 += k1 + 3u;
    TF_ROUND(17) TF_ROUND(29) TF_ROUND(16) TF_ROUND(24)
    x0 += k1;  x1 += ks2 + 4u;
    TF_ROUND(13) TF_ROUND(15) TF_ROUND(26) TF_ROUND(6)
    x0 += ks2; x1 += k0 + 5u;
#undef TF_ROUND
    o0 = x0; o1 = x1;
}

__device__ __forceinline__ unsigned jax_bits32(unsigned k0, unsigned k1, unsigned i) {
    unsigned o0, o1;
    tf2x32(k0, k1, 0u, i, o0, o1);
    return o0 ^ o1;
}

__device__ __forceinline__ uint32_t smem_u32(const void* p) {
    uint32_t a;
    asm("{ .reg .u64 t; cvta.to.shared.u64 t, %1; cvt.u32.u64 %0, t; }" : "=r"(a) : "l"(p));
    return a;
}

// ---------------- fp16 pack helpers ----------------
__device__ __forceinline__ unsigned pack_h2(float a, float b) {
    __half2 h = __floats2half2_rn(a, b);
    return *(unsigned*)&h;
}

__device__ __forceinline__ float2 unpack_h2(unsigned u) {
    return __half22float2(*(__half2*)&u);
}

// ---------------- CSR build ----------------
__global__ void zero_kernel() {
    int i = blockIdx.x * blockDim.x + threadIdx.x;
    if (i < NN) { g_cnt_a[i] = 0; g_cnt_b[i] = 0; g_cur_a[i] = 0; g_cur_b[i] = 0; }
}

__global__ void count_kernel(const int* __restrict__ dst_a, const int* __restrict__ dst_b) {
    int e = blockIdx.x * blockDim.x + threadIdx.x;
    if (e < EE) {
        atomicAdd(&g_cnt_a[dst_a[e]], 1);
        atomicAdd(&g_cnt_b[dst_b[e]], 1);
    }
}

__global__ void scan_pre() {
    int y = blockIdx.y;
    const int* cnt = y ? g_cnt_b : g_cnt_a;
    int* off = y ? g_off_b : g_off_a;
    __shared__ int sb[256];
    int t = threadIdx.x;
    int base = blockIdx.x * 1024 + t * 4;
    int v[4]; int s = 0;
#pragma unroll
    for (int i = 0; i < 4; i++) {
        int idx = base + i;
        v[i] = (idx < NN) ? cnt[idx] : 0;
        s += v[i];
    }
    sb[t] = s;
    __syncthreads();
    for (int d = 1; d < 256; d <<= 1) {
        int x = (t >= d) ? sb[t - d] : 0;
        __syncthreads();
        sb[t] += x;
        __syncthreads();
    }
    int run = sb[t] - s;
#pragma unroll
    for (int i = 0; i < 4; i++) {
        int idx = base + i;
        if (idx < NN) off[idx] = run;
        run += v[i];
    }
    if (t == 255) g_blk[y][blockIdx.x] = sb[255];
}

__global__ void scan_mid() {
    int y = blockIdx.y;
    int* off = y ? g_off_b : g_off_a;
    __shared__ int sb[64];
    int t = threadIdx.x;
    int v = (t < 49) ? g_blk[y][t] : 0;
    sb[t] = v;
    __syncthreads();
    for (int d = 1; d < 64; d <<= 1) {
        int x = (t >= d) ? sb[t - d] : 0;
        __syncthreads();
        sb[t] += x;
        __syncthreads();
    }
    if (t < 49) g_blkoff[y][t] = sb[t] - v;
    if (t == 63) off[NN] = sb[63];
}

__global__ void scan_add() {
    int y = blockIdx.y;
    int* off = y ? g_off_b : g_off_a;
    int add = g_blkoff[y][blockIdx.x];
    int base = blockIdx.x * 1024 + threadIdx.x * 4;
#pragma unroll
    for (int i = 0; i < 4; i++) {
        int idx = base + i;
        if (idx < NN) off[idx] += add;
    }
}

__global__ void fill_kernel(const int* __restrict__ src_a, const int* __restrict__ dst_a,
                            const int* __restrict__ src_b, const int* __restrict__ dst_b) {
    int e = blockIdx.x * blockDim.x + threadIdx.x;
    if (e < EE) {
        int da = dst_a[e];
        int pa = g_off_a[da] + atomicAdd(&g_cur_a[da], 1);
        g_csr_a[pa] = src_a[e];
        int db = dst_b[e];
        int pb = g_off_b[db] + atomicAdd(&g_cur_b[db], 1);
        g_csr_b[pb] = src_b[e];
    }
}

// ---------------- init out to broadcast bias ----------------
__global__ void initout_kernel(const float* __restrict__ bout, float* __restrict__ out) {
    int i = blockIdx.x * 256 + threadIdx.x;   // float4 index
    if (i < (NN * 16) / 4) {
        int j4 = (i & 3) * 4;
        ((float4*)out)[i] = make_float4(bout[j4], bout[j4 + 1], bout[j4 + 2], bout[j4 + 3]);
    }
}

// ---------------- input conversion fp32 -> fp16 ----------------
__global__ void conv_kernel(const float* __restrict__ xs, const float* __restrict__ xt) {
    int i = blockIdx.x * 256 + threadIdx.x;
    int base = i * 4;
    if (base >= TOT) return;
    const float* src = blockIdx.y ? xt : xs;
    __half* dst = blockIdx.y ? g_pxt : g_pxs;
    float4 v = *(const float4*)(src + base);
    uint2 o;
    o.x = pack_h2(v.x, v.y);
    o.y = pack_h2(v.z, v.w);
    ((uint2*)dst)[i] = o;
}

// ---------------- segment mean over fp16 activations (dual via blockIdx.y) ----------------
__global__ void segmean2_kernel(const __half* __restrict__ x0, const int* __restrict__ off0,
                                const int* __restrict__ csr0, __half* __restrict__ out0,
                                const __half* __restrict__ x1, const int* __restrict__ off1,
                                const int* __restrict__ csr1, __half* __restrict__ out1) {
    int y = blockIdx.y;
    const __half* x = y ? x1 : x0;
    const int* off = y ? off1 : off0;
    const int* csr = y ? csr1 : csr0;
    __half* out = y ? out1 : out0;
    int r = blockIdx.x;
    int t = threadIdx.x;  // 0..63, 4 elements each (uint2 = 4 halves)
    int s0 = off[r], s1 = off[r + 1];
    float a0 = 0.f, a1 = 0.f, a2 = 0.f, a3 = 0.f;
    float b0 = 0.f, b1 = 0.f, b2 = 0.f, b3 = 0.f;
    int e = s0;
    for (; e + 2 <= s1; e += 2) {
        int sA = csr[e], sB = csr[e + 1];
        uint2 p = __ldg((const uint2*)(x + (size_t)sA * DD) + t);
        uint2 q = __ldg((const uint2*)(x + (size_t)sB * DD) + t);
        float2 p0 = unpack_h2(p.x), p1 = unpack_h2(p.y);
        float2 q0 = unpack_h2(q.x), q1 = unpack_h2(q.y);
        a0 += p0.x; a1 += p0.y; a2 += p1.x; a3 += p1.y;
        b0 += q0.x; b1 += q0.y; b2 += q1.x; b3 += q1.y;
    }
    if (e < s1) {
        int sA = csr[e];
        uint2 p = __ldg((const uint2*)(x + (size_t)sA * DD) + t);
        float2 p0 = unpack_h2(p.x), p1 = unpack_h2(p.y);
        a0 += p0.x; a1 += p0.y; a2 += p1.x; a3 += p1.y;
    }
    a0 += b0; a1 += b1; a2 += b2; a3 += b3;
    int cnt = s1 - s0;
    float inv = 1.0f / (float)(cnt > 0 ? cnt : 1);
    uint2 o;
    o.x = pack_h2(a0 * inv, a1 * inv);
    o.y = pack_h2(a2 * inv, a3 * inv);
    ((uint2*)(out + (size_t)r * DD))[t] = o;
}

// ---------------- weight prep: transpose + fp32 -> fp16 ----------------
__global__ void wprep_kernel(const float* __restrict__ Wl_st, const float* __restrict__ Wr_st,
                             const float* __restrict__ Wl_ts, const float* __restrict__ Wr_ts) {
    int m = blockIdx.y;           // 0..7
    int layer = m >> 2, t = m & 3;
    const float* base = (t == 0) ? Wl_st : (t == 1) ? Wr_st : (t == 2) ? Wl_ts : Wr_ts;
    const float* W = base + layer * 65536;
    int idx = blockIdx.x * 256 + threadIdx.x;
    int n = idx >> 8, k = idx & 255;
    g_wfh[m * 65536 + idx] = __float2half_rn(W[k * 256 + n]);
}

// ---------------- mma.sync fp16 fused dual-GEMM + bias + leaky + dropout ----------------
// FUSE=true additionally computes out[r][0..15] += dropout_result_row @ Wout (no C store).
#define ASTRIDE 20            // u32 per 32-k row: 16 data + 4 pad
#define TILE_U32 2560         // 128 rows * 20 u32
#define ST_U32 (2 * TILE_U32) // A + B per stage = 5120 u32 (20 KB)
#define OFF_AH 0
#define OFF_BH TILE_U32
#define WS_OFF (3 * ST_U32)   // fp32 Wout slice [128][16] (FUSE only)
#define VSTRIDE 68            // v-tile row stride in u32 (64 data + 4 pad)
#define SMEM_GEMM   (3 * ST_U32 * 4)            // 61440 B
#define SMEM_GEMM_F (3 * ST_U32 * 4 + 8192)     // + fp32 Wout slice

#define LDSM4(r0, r1, r2, r3, addr) \
    asm volatile("ldmatrix.sync.aligned.m8n8.x4.shared.b16 {%0,%1,%2,%3}, [%4];" \
                 : "=r"(r0), "=r"(r1), "=r"(r2), "=r"(r3) : "r"(addr))

#define MMA16816(c, a, b0, b1) \
    asm volatile("mma.sync.aligned.m16n8k16.row.col.f32.f16.f16.f32 " \
                 "{%0,%1,%2,%3}, {%4,%5,%6,%7}, {%8,%9}, {%0,%1,%2,%3};" \
                 : "+f"((c)[0]), "+f"((c)[1]), "+f"((c)[2]), "+f"((c)[3]) \
                 : "r"((a)[0]), "r"((a)[1]), "r"((a)[2]), "r"((a)[3]), "r"(b0), "r"(b1))

struct GArgs {
    const __half *A1, *A2;
    const __half *W1h, *W2h;
    const float* bias;
    __half* outC;
    const float* Wproj;   // FUSE: Wout [256][16]
    float* outF;          // FUSE: out [M][16]
    unsigned dk0, dk1;
};

template <bool FUSE>
__global__ void __launch_bounds__(256, 2) gemm_mma(GArgs ga, GArgs gb, int M) {
    extern __shared__ uint32_t sm[];
    const GArgs g = blockIdx.z ? gb : ga;
    const __half* __restrict__ A1 = g.A1;
    const __half* __restrict__ A2 = g.A2;
    const __half* __restrict__ W1h = g.W1h;
    const __half* __restrict__ W2h = g.W2h;
    const float* __restrict__ bias = g.bias;
    __half* __restrict__ C = g.outC;
    const unsigned dk0 = g.dk0, dk1 = g.dk1;

    const int tid = threadIdx.x;
    const int lane = tid & 31, wid = tid >> 5;
    const int warpM = wid & 3, warpN = wid >> 2;      // 4 x 2 warps
    const int rowBase = blockIdx.y * MTILE;
    const int colBase = blockIdx.x * 128;
    const uint32_t smaddr = smem_u32(sm);

    if (FUSE) {
        // load Wout slice for this CTA's 128 cols: [128][16] fp32
        float* WsS = (float*)(sm + WS_OFF);
        const uint4* src = (const uint4*)(g.Wproj + (size_t)colBase * 16);
#pragma unroll
        for (int i = 0; i < 2; i++)
            ((uint4*)WsS)[tid + i * 256] = src[tid + i * 256];
    }

    float acc[2][8][4];
#pragma unroll
    for (int i = 0; i < 2; i++)
#pragma unroll
        for (int j = 0; j < 8; j++)
#pragma unroll
            for (int q = 0; q < 4; q++) acc[i][j][q] = 0.f;

    uint4 aReg[2];
    uint4 bReg[2];

    uint32_t aAddr[2][2], bAddr[4][2];
#pragma unroll
    for (int mt = 0; mt < 2; mt++)
#pragma unroll
        for (int ks = 0; ks < 2; ks++) {
            int row = warpM * 32 + mt * 16 + (lane & 15);
            int kOff = ks * 16 + (lane >> 4) * 8;
            aAddr[mt][ks] = smaddr + (uint32_t)(OFF_AH + row * ASTRIDE + (kOff >> 1)) * 4;
        }
#pragma unroll
    for (int np = 0; np < 4; np++)
#pragma unroll
        for (int ks = 0; ks < 2; ks++) {
            int n = warpN * 64 + np * 16 + (lane & 7) + (lane >> 4) * 8;
            int kOff = ks * 16 + ((lane >> 3) & 1) * 8;
            bAddr[np][ks] = smaddr + (uint32_t)(OFF_BH + n * ASTRIDE + (kOff >> 1)) * 4;
        }

#define GLOAD(c) do { \
        int mat_ = (c) >> 3; int kb_ = ((c) & 7) * 32; \
        const __half* A_ = mat_ ? A2 : A1; \
        const __half* Bh_ = mat_ ? W2h : W1h; \
        _Pragma("unroll") \
        for (int j = 0; j < 2; j++) { \
            int idx = tid + j * 256; \
            int r = idx >> 2, seg = idx & 3; \
            int gr = rowBase + r; \
            aReg[j] = (gr < M) ? *(const uint4*)(A_ + (size_t)gr * 256 + kb_ + seg * 8) \
                               : make_uint4(0u, 0u, 0u, 0u); \
        } \
        _Pragma("unroll") \
        for (int j = 0; j < 2; j++) { \
            int idx = tid + j * 256; \
            int n = idx >> 2, ko = (idx & 3) * 8; \
            bReg[j] = *(const uint4*)(Bh_ + (size_t)(colBase + n) * 256 + kb_ + ko); \
        } \
    } while (0)

#define SSTORE(st) do { \
        uint32_t* base_ = sm + (st) * ST_U32; \
        _Pragma("unroll") \
        for (int j = 0; j < 2; j++) { \
            int idx = tid + j * 256; \
            int r = idx >> 2, seg = idx & 3; \
            *(uint4*)(base_ + OFF_AH + r * ASTRIDE + seg * 4) = aReg[j]; \
        } \
        _Pragma("unroll") \
        for (int j = 0; j < 2; j++) { \
            int idx = tid + j * 256; \
            int n = idx >> 2, ko = (idx & 3) * 8; \
            *(uint4*)(base_ + OFF_BH + n * ASTRIDE + (ko >> 1)) = bReg[j]; \
        } \
    } while (0)

    GLOAD(0);
    SSTORE(0);
    __syncthreads();

#pragma unroll 1
    for (int c = 0; c < 16; c++) {
        if (c < 15) GLOAD(c + 1);
        const uint32_t stOff = (uint32_t)(c % 3) * (ST_U32 * 4);
#pragma unroll
        for (int ks = 0; ks < 2; ks++) {
            uint32_t ah[2][4], bh[4][4];
#pragma unroll
            for (int mt = 0; mt < 2; mt++) {
                uint32_t ad = aAddr[mt][ks] + stOff;
                LDSM4(ah[mt][0], ah[mt][1], ah[mt][2], ah[mt][3], ad);
            }
#pragma unroll
            for (int np = 0; np < 4; np++) {
                uint32_t bd = bAddr[np][ks] + stOff;
                LDSM4(bh[np][0], bh[np][1], bh[np][2], bh[np][3], bd);
            }
#pragma unroll
            for (int mt = 0; mt < 2; mt++)
#pragma unroll
                for (int nt = 0; nt < 8; nt++) {
                    int grp = nt >> 1, pr = (nt & 1) * 2;
                    MMA16816(acc[mt][nt], ah[mt], bh[grp][pr], bh[grp][pr + 1]);
                }
        }
        if (c < 15) SSTORE((c + 1) % 3);
        __syncthreads();
    }

    // epilogue: bias + leaky-relu + dropout
    const float sc = 1.0f / 0.9f;
#pragma unroll
    for (int mt = 0; mt < 2; mt++)
#pragma unroll
        for (int nt = 0; nt < 8; nt++) {
            int colL = warpN * 64 + nt * 8 + (lane & 3) * 2;
            int col = colBase + colL;
            float2 bv = *(const float2*)(bias + col);
#pragma unroll
            for (int half = 0; half < 2; half++) {
                int rL = warpM * 32 + mt * 16 + (lane >> 2) + half * 8;
                int r = rowBase + rL;
                float v0 = acc[mt][nt][half * 2 + 0] + bv.x;
                float v1 = acc[mt][nt][half * 2 + 1] + bv.y;
                v0 = v0 >= 0.f ? v0 : 0.01f * v0;
                v1 = v1 >= 0.f ? v1 : 0.01f * v1;
                unsigned i0 = (unsigned)r * 256u + (unsigned)col;
                unsigned q0 = jax_bits32(dk0, dk1, i0);
                unsigned q1 = jax_bits32(dk0, dk1, i0 + 1u);
                float u0 = __uint_as_float((q0 >> 9) | 0x3f800000u) - 1.0f;
                float u1 = __uint_as_float((q1 >> 9) | 0x3f800000u) - 1.0f;
                v0 = (u0 < 0.9f) ? v0 * sc : 0.0f;
                v1 = (u1 < 0.9f) ? v1 * sc : 0.0f;
                if (FUSE) {
                    sm[rL * VSTRIDE + (colL >> 1)] = pack_h2(v0, v1);
                } else {
                    if (r < M)
                        *(unsigned*)(C + (size_t)r * 256 + col) = pack_h2(v0, v1);
                }
            }
        }

    if (FUSE) {
        __syncthreads();
        // cooperative projection: out[r][0..15] += vrow(128 cols) @ WsS(128x16)
        const float* WsS = (const float*)(sm + WS_OFF);
        int rL = tid >> 1;                 // 0..127
        int jB = (tid & 1) * 8;
        int r = rowBase + rL;
        float pr[8];
#pragma unroll
        for (int j = 0; j < 8; j++) pr[j] = 0.f;
        const uint32_t* vrow = sm + rL * VSTRIDE;
#pragma unroll 4
        for (int k = 0; k < 128; k += 4) {
            uint2 pv = *(const uint2*)(vrow + (k >> 1));
            float2 f0 = unpack_h2(pv.x), f1 = unpack_h2(pv.y);
#pragma unroll
            for (int j = 0; j < 8; j++) {
                pr[j] += f0.x * WsS[(k + 0) * 16 + jB + j];
                pr[j] += f0.y * WsS[(k + 1) * 16 + jB + j];
                pr[j] += f1.x * WsS[(k + 2) * 16 + jB + j];
                pr[j] += f1.y * WsS[(k + 3) * 16 + jB + j];
            }
        }
        if (r < M) {
            float* o = g.outF + (size_t)r * 16 + jB;
#pragma unroll
            for (int j = 0; j < 8; j++) atomicAdd(o + j, pr[j]);
        }
    }
}

// ---------------- host ----------------
extern "C" void kernel_launch(void* const* d_in, const int* in_sizes, int n_in,
                              void* d_out, int out_size) {
    const float* x_source = (const float*)d_in[0];
    const float* x_target = (const float*)d_in[1];
    const int* ei_st = (const int*)d_in[2];
    const int* ei_ts = (const int*)d_in[3];
    const float* Wl_st = (const float*)d_in[4];
    const float* Wr_st = (const float*)d_in[5];
    const float* b_st = (const float*)d_in[6];
    const float* Wl_ts = (const float*)d_in[7];
    const float* Wr_ts = (const float*)d_in[8];
    const float* b_ts = (const float*)d_in[9];
    const float* Wout = (const float*)d_in[10];
    const float* bout = (const float*)d_in[11];
    float* out = (float*)d_out;

    void* p;
    __half *pxs, *pxt, *pma, *pmb, *pxt0, *pxs0, *wfh;
    cudaGetSymbolAddress(&p, g_pxs);  pxs = (__half*)p;
    cudaGetSymbolAddress(&p, g_pxt);  pxt = (__half*)p;
    cudaGetSymbolAddress(&p, g_pma);  pma = (__half*)p;
    cudaGetSymbolAddress(&p, g_pmb);  pmb = (__half*)p;
    cudaGetSymbolAddress(&p, g_pxt0); pxt0 = (__half*)p;
    cudaGetSymbolAddress(&p, g_pxs0); pxs0 = (__half*)p;
    cudaGetSymbolAddress(&p, g_wfh);  wfh = (__half*)p;
    int *off_a, *off_b, *csr_a, *csr_b;
    cudaGetSymbolAddress(&p, g_off_a); off_a = (int*)p;
    cudaGetSymbolAddress(&p, g_off_b); off_b = (int*)p;
    cudaGetSymbolAddress(&p, g_csr_a); csr_a = (int*)p;
    cudaGetSymbolAddress(&p, g_csr_b); csr_b = (int*)p;

    cudaFuncSetAttribute(gemm_mma<false>, cudaFuncAttributeMaxDynamicSharedMemorySize, SMEM_GEMM);
    cudaFuncSetAttribute(gemm_mma<true>, cudaFuncAttributeMaxDynamicSharedMemorySize, SMEM_GEMM_F);

    const int* src_st = ei_st;
    const int* dst_st = ei_st + EE;
    const int* src_ts = ei_ts;
    const int* dst_ts = ei_ts + EE;

    // dropout keys: fold_in(key(42)=(0,42), d); d=0 -> xs0, d=1 -> xt0, d=2 -> xs1
    unsigned dkeys[3][2];
    for (int d = 0; d < 3; d++)
        tf2x32(0u, 42u, 0u, (unsigned)d, dkeys[d][0], dkeys[d][1]);

    wprep_kernel<<<dim3(256, 8), 256>>>(Wl_st, Wr_st, Wl_ts, Wr_ts);
    conv_kernel<<<dim3(12500, 2), 256>>>(x_source, x_target);
    zero_kernel<<<(NN + 255) / 256, 256>>>();
    initout_kernel<<<(NN * 16 / 4 + 255) / 256, 256>>>(bout, out);
    count_kernel<<<(EE + 255) / 256, 256>>>(dst_st, dst_ts);
    scan_pre<<<dim3(49, 2), 256>>>();
    scan_mid<<<dim3(1, 2), 64>>>();
    scan_add<<<dim3(49, 2), 256>>>();
    fill_kernel<<<(EE + 255) / 256, 256>>>(src_st, dst_st, src_ts, dst_ts);

    const int M64K = 65536;

    // ---- layer 0: both segmeans in one launch, both gemms in one launch ----
    segmean2_kernel<<<dim3(NN, 2), 64>>>(pxs, off_a, csr_a, pma,
                                         pxt, off_b, csr_b, pmb);
    GArgs gA = {}, gB = {};
    // z=0: new_t = m_t@Wl_st + x_t@Wr_st + b_st -> pxt0 (key d=1)
    gA.A1 = pma; gA.A2 = pxt;
    gA.W1h = wfh + 0 * M64K; gA.W2h = wfh + 1 * M64K;
    gA.bias = b_st; gA.outC = pxt0; gA.dk0 = dkeys[1][0]; gA.dk1 = dkeys[1][1];
    // z=1: new_s = m_s@Wl_ts + x_s@Wr_ts + b_ts -> pxs0 (key d=0)
    gB.A1 = pmb; gB.A2 = pxs;
    gB.W1h = wfh + 2 * M64K; gB.W2h = wfh + 3 * M64K;
    gB.bias = b_ts; gB.outC = pxs0; gB.dk0 = dkeys[0][0]; gB.dk1 = dkeys[0][1];
    gemm_mma<false><<<dim3(2, NBLKY, 2), 256, SMEM_GEMM>>>(gA, gB, NN);

    // ---- layer 1 (target branch dead); projection fused into gemm epilogue ----
    segmean2_kernel<<<dim3(NN, 1), 64>>>(pxt0, off_b, csr_b, pma,
                                         pxt0, off_b, csr_b, pma);
    GArgs gC = {};
    gC.A1 = pma; gC.A2 = pxs0;
    gC.W1h = wfh + 6 * M64K; gC.W2h = wfh + 7 * M64K;
    gC.bias = b_ts + 256; gC.outC = nullptr;
    gC.Wproj = Wout; gC.outF = out;
    gC.dk0 = dkeys[2][0]; gC.dk1 = dkeys[2][1];
    gemm_mma<true><<<dim3(2, NBLKY, 1), 256, SMEM_GEMM_F>>>(gC, gC, NN);
}

// round 12
// speedup vs baseline: 1.9416x; 1.0161x over previous
#include <cuda_runtime.h>
#include <cuda_fp16.h>
#include <cstdint>

#define NN 50000
#define DD 256
#define EE 320000
#define TOT (NN * DD)
#define MTILE 128
#define NBLKY ((NN + MTILE - 1) / MTILE)   // 391

// ---------------- scratch (static __device__ — no allocation allowed) ----------------
__device__ int g_cnt_a[NN], g_cnt_b[NN], g_cur_a[NN], g_cur_b[NN];
__device__ int g_off_a[NN + 1], g_off_b[NN + 1];
__device__ int g_csr_a[EE], g_csr_b[EE];
__device__ int g_blk[2][49], g_blkoff[2][49];
// pure fp16 activations
__device__ __half g_pxs[TOT], g_pxt[TOT];
__device__ __half g_pma[TOT], g_pmb[TOT];
__device__ __half g_pxt0[TOT], g_pxs0[TOT];
// pre-transposed fp16 weights: 8 matrices [n=256][k=256]
__device__ __half g_wfh[8 * 65536];

// ---------------- threefry-2x32 (exactly JAX's) ----------------
__host__ __device__ __forceinline__ unsigned rotl32(unsigned x, int d) {
    return (x << d) | (x >> (32 - d));
}

__host__ __device__ __forceinline__ void tf2x32(unsigned k0, unsigned k1,
                                                unsigned x0, unsigned x1,
                                                unsigned& o0, unsigned& o1) {
    unsigned ks2 = k0 ^ k1 ^ 0x1BD11BDAu;
    x0 += k0; x1 += k1;
#define TF_ROUND(r) { x0 += x1; x1 = rotl32(x1, r); x1 ^= x0; }
    TF_ROUND(13) TF_ROUND(15) TF_ROUND(26) TF_ROUND(6)
    x0 += k1;  x1 += ks2 + 1u;
    TF_ROUND(17) TF_ROUND(29) TF_ROUND(16) TF_ROUND(24)
    x0 += ks2; x1 += k0 + 2u;
    TF_ROUND(13) TF_ROUND(15) TF_ROUND(26) TF_ROUND(6)
    x0 += k0;  x1 += k1 + 3u;
    TF_ROUND(17) TF_ROUND(29) TF_ROUND(16) TF_ROUND(24)
    x0 += k1;  x1 += ks2 + 4u;
    TF_ROUND(13) TF_ROUND(15) TF_ROUND(26) TF_ROUND(6)
    x0 += ks2; x1 += k0 + 5u;
#undef TF_ROUND
    o0 = x0; o1 = x1;
}

__device__ __forceinline__ unsigned jax_bits32(unsigned k0, unsigned k1, unsigned i) {
    unsigned o0, o1;
    tf2x32(k0, k1, 0u, i, o0, o1);
    return o0 ^ o1;
}

__device__ __forceinline__ uint32_t smem_u32(const void* p) {
    uint32_t a;
    asm("{ .reg .u64 t; cvta.to.shared.u64 t, %1; cvt.u32.u64 %0, t; }" : "=r"(a) : "l"(p));
    return a;
}

// ---------------- fp16 pack helpers ----------------
__device__ __forceinline__ unsigned pack_h2(float a, float b) {
    __half2 h = __floats2half2_rn(a, b);
    return *(unsigned*)&h;
}

__device__ __forceinline__ float2 unpack_h2(unsigned u) {
    return __half22float2(*(__half2*)&u);
}

// ---------------- init: zero counters + out := broadcast bias ----------------
__global__ void init_kernel(const float* __restrict__ bout, float* __restrict__ out) {
    int i = blockIdx.x * 256 + threadIdx.x;
    if (i < NN) { g_cnt_a[i] = 0; g_cnt_b[i] = 0; g_cur_a[i] = 0; g_cur_b[i] = 0; }
    if (i < (NN * 16) / 4) {
        int j4 = (i & 3) * 4;
        ((float4*)out)[i] = make_float4(bout[j4], bout[j4 + 1], bout[j4 + 2], bout[j4 + 3]);
    }
}

__global__ void count_kernel(const int* __restrict__ dst_a, const int* __restrict__ dst_b) {
    int e = blockIdx.x * blockDim.x + threadIdx.x;
    if (e < EE) {
        atomicAdd(&g_cnt_a[dst_a[e]], 1);
        atomicAdd(&g_cnt_b[dst_b[e]], 1);
    }
}

__global__ void scan_pre() {
    int y = blockIdx.y;
    const int* cnt = y ? g_cnt_b : g_cnt_a;
    int* off = y ? g_off_b : g_off_a;
    __shared__ int sb[256];
    int t = threadIdx.x;
    int base = blockIdx.x * 1024 + t * 4;
    int v[4]; int s = 0;
#pragma unroll
    for (int i = 0; i < 4; i++) {
        int idx = base + i;
        v[i] = (idx < NN) ? cnt[idx] : 0;
        s += v[i];
    }
    sb[t] = s;
    __syncthreads();
    for (int d = 1; d < 256; d <<= 1) {
        int x = (t >= d) ? sb[t - d] : 0;
        __syncthreads();
        sb[t] += x;
        __syncthreads();
    }
    int run = sb[t] - s;
#pragma unroll
    for (int i = 0; i < 4; i++) {
        int idx = base + i;
        if (idx < NN) off[idx] = run;
        run += v[i];
    }
    if (t == 255) g_blk[y][blockIdx.x] = sb[255];
}

__global__ void scan_mid() {
    int y = blockIdx.y;
    int* off = y ? g_off_b : g_off_a;
    __shared__ int sb[64];
    int t = threadIdx.x;
    int v = (t < 49) ? g_blk[y][t] : 0;
    sb[t] = v;
    __syncthreads();
    for (int d = 1; d < 64; d <<= 1) {
        int x = (t >= d) ? sb[t - d] : 0;
        __syncthreads();
        sb[t] += x;
        __syncthreads();
    }
    if (t < 49) g_blkoff[y][t] = sb[t] - v;
    if (t == 63) off[NN] = sb[63];
}

__global__ void scan_add() {
    int y = blockIdx.y;
    int* off = y ? g_off_b : g_off_a;
    int add = g_blkoff[y][blockIdx.x];
    int base = blockIdx.x * 1024 + threadIdx.x * 4;
#pragma unroll
    for (int i = 0; i < 4; i++) {
        int idx = base + i;
        if (idx < NN) off[idx] += add;
    }
}

__global__ void fill_kernel(const int* __restrict__ src_a, const int* __restrict__ dst_a,
                            const int* __restrict__ src_b, const int* __restrict__ dst_b) {
    int e = blockIdx.x * blockDim.x + threadIdx.x;
    if (e < EE) {
        int da = dst_a[e];
        int pa = g_off_a[da] + atomicAdd(&g_cur_a[da], 1);
        g_csr_a[pa] = src_a[e];
        int db = dst_b[e];
        int pb = g_off_b[db] + atomicAdd(&g_cur_b[db], 1);
        g_csr_b[pb] = src_b[e];
    }
}

// ---------------- input conversion fp32 -> fp16 ----------------
__global__ void conv_kernel(const float* __restrict__ xs, const float* __restrict__ xt) {
    int i = blockIdx.x * 256 + threadIdx.x;
    int base = i * 4;
    if (base >= TOT) return;
    const float* src = blockIdx.y ? xt : xs;
    __half* dst = blockIdx.y ? g_pxt : g_pxs;
    float4 v = *(const float4*)(src + base);
    uint2 o;
    o.x = pack_h2(v.x, v.y);
    o.y = pack_h2(v.z, v.w);
    ((uint2*)dst)[i] = o;
}

// ---------------- segment mean: warp-per-row, 8 rows/block (dual via blockIdx.y) ----------------
__global__ void __launch_bounds__(256) segmean2_kernel(
    const __half* __restrict__ x0, const int* __restrict__ off0,
    const int* __restrict__ csr0, __half* __restrict__ out0,
    const __half* __restrict__ x1, const int* __restrict__ off1,
    const int* __restrict__ csr1, __half* __restrict__ out1) {
    int y = blockIdx.y;
    const __half* x = y ? x1 : x0;
    const int* off = y ? off1 : off0;
    const int* csr = y ? csr1 : csr0;
    __half* out = y ? out1 : out0;
    int warp = threadIdx.x >> 5, lane = threadIdx.x & 31;
    int r = blockIdx.x * 8 + warp;
    if (r >= NN) return;
    int s0 = off[r], s1 = off[r + 1];
    // lane owns 8 halves (uint4 = 16B); 32 lanes cover the full 256-wide row
    float a[8] = {0.f, 0.f, 0.f, 0.f, 0.f, 0.f, 0.f, 0.f};
    float b[8] = {0.f, 0.f, 0.f, 0.f, 0.f, 0.f, 0.f, 0.f};
    int e = s0;
    for (; e + 2 <= s1; e += 2) {
        int sA = csr[e], sB = csr[e + 1];
        uint4 p = __ldg((const uint4*)(x + (size_t)sA * DD) + lane);
        uint4 q = __ldg((const uint4*)(x + (size_t)sB * DD) + lane);
        float2 f;
        f = unpack_h2(p.x); a[0] += f.x; a[1] += f.y;
        f = unpack_h2(p.y); a[2] += f.x; a[3] += f.y;
        f = unpack_h2(p.z); a[4] += f.x; a[5] += f.y;
        f = unpack_h2(p.w); a[6] += f.x; a[7] += f.y;
        f = unpack_h2(q.x); b[0] += f.x; b[1] += f.y;
        f = unpack_h2(q.y); b[2] += f.x; b[3] += f.y;
        f = unpack_h2(q.z); b[4] += f.x; b[5] += f.y;
        f = unpack_h2(q.w); b[6] += f.x; b[7] += f.y;
    }
    if (e < s1) {
        int sA = csr[e];
        uint4 p = __ldg((const uint4*)(x + (size_t)sA * DD) + lane);
        float2 f;
        f = unpack_h2(p.x); a[0] += f.x; a[1] += f.y;
        f = unpack_h2(p.y); a[2] += f.x; a[3] += f.y;
        f = unpack_h2(p.z); a[4] += f.x; a[5] += f.y;
        f = unpack_h2(p.w); a[6] += f.x; a[7] += f.y;
    }
#pragma unroll
    for (int j = 0; j < 8; j++) a[j] += b[j];
    int cnt = s1 - s0;
    float inv = 1.0f / (float)(cnt > 0 ? cnt : 1);
    uint4 o;
    o.x = pack_h2(a[0] * inv, a[1] * inv);
    o.y = pack_h2(a[2] * inv, a[3] * inv);
    o.z = pack_h2(a[4] * inv, a[5] * inv);
    o.w = pack_h2(a[6] * inv, a[7] * inv);
    ((uint4*)(out + (size_t)r * DD))[lane] = o;
}

// ---------------- weight prep: transpose + fp32 -> fp16 ----------------
__global__ void wprep_kernel(const float* __restrict__ Wl_st, const float* __restrict__ Wr_st,
                             const float* __restrict__ Wl_ts, const float* __restrict__ Wr_ts) {
    int m = blockIdx.y;           // 0..7
    int layer = m >> 2, t = m & 3;
    const float* base = (t == 0) ? Wl_st : (t == 1) ? Wr_st : (t == 2) ? Wl_ts : Wr_ts;
    const float* W = base + layer * 65536;
    int idx = blockIdx.x * 256 + threadIdx.x;
    int n = idx >> 8, k = idx & 255;
    g_wfh[m * 65536 + idx] = __float2half_rn(W[k * 256 + n]);
}

// ---------------- mma.sync fp16 fused dual-GEMM + bias + leaky + dropout ----------------
// FUSE=true additionally computes out[r][0..15] += dropout_result_row @ Wout (no C store).
#define ASTRIDE 20            // u32 per 32-k row: 16 data + 4 pad
#define TILE_U32 2560         // 128 rows * 20 u32
#define ST_U32 (2 * TILE_U32) // A + B per stage = 5120 u32 (20 KB)
#define OFF_AH 0
#define OFF_BH TILE_U32
#define WS_OFF (3 * ST_U32)   // fp32 Wout slice [128][16] (FUSE only)
#define VSTRIDE 68            // v-tile row stride in u32 (64 data + 4 pad)
#define SMEM_GEMM   (3 * ST_U32 * 4)            // 61440 B
#define SMEM_GEMM_F (3 * ST_U32 * 4 + 8192)     // + fp32 Wout slice

#define LDSM4(r0, r1, r2, r3, addr) \
    asm volatile("ldmatrix.sync.aligned.m8n8.x4.shared.b16 {%0,%1,%2,%3}, [%4];" \
                 : "=r"(r0), "=r"(r1), "=r"(r2), "=r"(r3) : "r"(addr))

#define MMA16816(c, a, b0, b1) \
    asm volatile("mma.sync.aligned.m16n8k16.row.col.f32.f16.f16.f32 " \
                 "{%0,%1,%2,%3}, {%4,%5,%6,%7}, {%8,%9}, {%0,%1,%2,%3};" \
                 : "+f"((c)[0]), "+f"((c)[1]), "+f"((c)[2]), "+f"((c)[3]) \
                 : "r"((a)[0]), "r"((a)[1]), "r"((a)[2]), "r"((a)[3]), "r"(b0), "r"(b1))

struct GArgs {
    const __half *A1, *A2;
    const __half *W1h, *W2h;
    const float* bias;
    __half* outC;
    const float* Wproj;   // FUSE: Wout [256][16]
    float* outF;          // FUSE: out [M][16]
    unsigned dk0, dk1;
};

template <bool FUSE>
__global__ void __launch_bounds__(256, 2) gemm_mma(GArgs ga, GArgs gb, int M) {
    extern __shared__ uint32_t sm[];
    const GArgs g = blockIdx.z ? gb : ga;
    const __half* __restrict__ A1 = g.A1;
    const __half* __restrict__ A2 = g.A2;
    const __half* __restrict__ W1h = g.W1h;
    const __half* __restrict__ W2h = g.W2h;
    const float* __restrict__ bias = g.bias;
    __half* __restrict__ C = g.outC;
    const unsigned dk0 = g.dk0, dk1 = g.dk1;

    const int tid = threadIdx.x;
    const int lane = tid & 31, wid = tid >> 5;
    const int warpM = wid & 3, warpN = wid >> 2;      // 4 x 2 warps
    const int rowBase = blockIdx.y * MTILE;
    const int colBase = blockIdx.x * 128;
    const uint32_t smaddr = smem_u32(sm);

    if (FUSE) {
        // load Wout slice for this CTA's 128 cols: [128][16] fp32
        float* WsS = (float*)(sm + WS_OFF);
        const uint4* src = (const uint4*)(g.Wproj + (size_t)colBase * 16);
#pragma unroll
        for (int i = 0; i < 2; i++)
            ((uint4*)WsS)[tid + i * 256] = src[tid + i * 256];
    }

    float acc[2][8][4];
#pragma unroll
    for (int i = 0; i < 2; i++)
#pragma unroll
        for (int j = 0; j < 8; j++)
#pragma unroll
            for (int q = 0; q < 4; q++) acc[i][j][q] = 0.f;

    uint4 aReg[2];
    uint4 bReg[2];

    uint32_t aAddr[2][2], bAddr[4][2];
#pragma unroll
    for (int mt = 0; mt < 2; mt++)
#pragma unroll
        for (int ks = 0; ks < 2; ks++) {
            int row = warpM * 32 + mt * 16 + (lane & 15);
            int kOff = ks * 16 + (lane >> 4) * 8;
            aAddr[mt][ks] = smaddr + (uint32_t)(OFF_AH + row * ASTRIDE + (kOff >> 1)) * 4;
        }
#pragma unroll
    for (int np = 0; np < 4; np++)
#pragma unroll
        for (int ks = 0; ks < 2; ks++) {
            int n = warpN * 64 + np * 16 + (lane & 7) + (lane >> 4) * 8;
            int kOff = ks * 16 + ((lane >> 3) & 1) * 8;
            bAddr[np][ks] = smaddr + (uint32_t)(OFF_BH + n * ASTRIDE + (kOff >> 1)) * 4;
        }

#define GLOAD(c) do { \
        int mat_ = (c) >> 3; int kb_ = ((c) & 7) * 32; \
        const __half* A_ = mat_ ? A2 : A1; \
        const __half* Bh_ = mat_ ? W2h : W1h; \
        _Pragma("unroll") \
        for (int j = 0; j < 2; j++) { \
            int idx = tid + j * 256; \
            int r = idx >> 2, seg = idx & 3; \
            int gr = rowBase + r; \
            aReg[j] = (gr < M) ? *(const uint4*)(A_ + (size_t)gr * 256 + kb_ + seg * 8) \
                               : make_uint4(0u, 0u, 0u, 0u); \
        } \
        _Pragma("unroll") \
        for (int j = 0; j < 2; j++) { \
            int idx = tid + j * 256; \
            int n = idx >> 2, ko = (idx & 3) * 8; \
            bReg[j] = *(const uint4*)(Bh_ + (size_t)(colBase + n) * 256 + kb_ + ko); \
        } \
    } while (0)

#define SSTORE(st) do { \
        uint32_t* base_ = sm + (st) * ST_U32; \
        _Pragma("unroll") \
        for (int j = 0; j < 2; j++) { \
            int idx = tid + j * 256; \
            int r = idx >> 2, seg = idx & 3; \
            *(uint4*)(base_ + OFF_AH + r * ASTRIDE + seg * 4) = aReg[j]; \
        } \
        _Pragma("unroll") \
        for (int j = 0; j < 2; j++) { \
            int idx = tid + j * 256; \
            int n = idx >> 2, ko = (idx & 3) * 8; \
            *(uint4*)(base_ + OFF_BH + n * ASTRIDE + (ko >> 1)) = bReg[j]; \
        } \
    } while (0)

    GLOAD(0);
    SSTORE(0);
    __syncthreads();

#pragma unroll 1
    for (int c = 0; c < 16; c++) {
        if (c < 15) GLOAD(c + 1);
        const uint32_t stOff = (uint32_t)(c % 3) * (ST_U32 * 4);
#pragma unroll
        for (int ks = 0; ks < 2; ks++) {
            uint32_t ah[2][4], bh[4][4];
#pragma unroll
            for (int mt = 0; mt < 2; mt++) {
                uint32_t ad = aAddr[mt][ks] + stOff;
                LDSM4(ah[mt][0], ah[mt][1], ah[mt][2], ah[mt][3], ad);
            }
#pragma unroll
            for (int np = 0; np < 4; np++) {
                uint32_t bd = bAddr[np][ks] + stOff;
                LDSM4(bh[np][0], bh[np][1], bh[np][2], bh[np][3], bd);
            }
#pragma unroll
            for (int mt = 0; mt < 2; mt++)
#pragma unroll
                for (int nt = 0; nt < 8; nt++) {
                    int grp = nt >> 1, pr = (nt & 1) * 2;
                    MMA16816(acc[mt][nt], ah[mt], bh[grp][pr], bh[grp][pr + 1]);
                }
        }
        if (c < 15) SSTORE((c + 1) % 3);
        __syncthreads();
    }

    // epilogue: bias + leaky-relu + dropout
    const float sc = 1.0f / 0.9f;
#pragma unroll
    for (int mt = 0; mt < 2; mt++)
#pragma unroll
        for (int nt = 0; nt < 8; nt++) {
            int colL = warpN * 64 + nt * 8 + (lane & 3) * 2;
            int col = colBase + colL;
            float2 bv = *(const float2*)(bias + col);
#pragma unroll
            for (int half = 0; half < 2; half++) {
                int rL = warpM * 32 + mt * 16 + (lane >> 2) + half * 8;
                int r = rowBase + rL;
                float v0 = acc[mt][nt][half * 2 + 0] + bv.x;
                float v1 = acc[mt][nt][half * 2 + 1] + bv.y;
                v0 = v0 >= 0.f ? v0 : 0.01f * v0;
                v1 = v1 >= 0.f ? v1 : 0.01f * v1;
                unsigned i0 = (unsigned)r * 256u + (unsigned)col;
                unsigned q0 = jax_bits32(dk0, dk1, i0);
                unsigned q1 = jax_bits32(dk0, dk1, i0 + 1u);
                float u0 = __uint_as_float((q0 >> 9) | 0x3f800000u) - 1.0f;
                float u1 = __uint_as_float((q1 >> 9) | 0x3f800000u) - 1.0f;
                v0 = (u0 < 0.9f) ? v0 * sc : 0.0f;
                v1 = (u1 < 0.9f) ? v1 * sc : 0.0f;
                if (FUSE) {
                    sm[rL * VSTRIDE + (colL >> 1)] = pack_h2(v0, v1);
                } else {
                    if (r < M)
                        *(unsigned*)(C + (size_t)r * 256 + col) = pack_h2(v0, v1);
                }
            }
        }

    if (FUSE) {
        __syncthreads();
        // cooperative projection: out[r][0..15] += vrow(128 cols) @ WsS(128x16)
        const float* WsS = (const float*)(sm + WS_OFF);
        int rL = tid >> 1;                 // 0..127
        int jB = (tid & 1) * 8;
        int r = rowBase + rL;
        float pr[8];
#pragma unroll
        for (int j = 0; j < 8; j++) pr[j] = 0.f;
        const uint32_t* vrow = sm + rL * VSTRIDE;
#pragma unroll 4
        for (int k = 0; k < 128; k += 4) {
            uint2 pv = *(const uint2*)(vrow + (k >> 1));
            float2 f0 = unpack_h2(pv.x), f1 = unpack_h2(pv.y);
#pragma unroll
            for (int j = 0; j < 8; j++) {
                pr[j] += f0.x * WsS[(k + 0) * 16 + jB + j];
                pr[j] += f0.y * WsS[(k + 1) * 16 + jB + j];
                pr[j] += f1.x * WsS[(k + 2) * 16 + jB + j];
                pr[j] += f1.y * WsS[(k + 3) * 16 + jB + j];
            }
        }
        if (r < M) {
            float* o = g.outF + (size_t)r * 16 + jB;
#pragma unroll
            for (int j = 0; j < 8; j++) atomicAdd(o + j, pr[j]);
        }
    }
}

// ---------------- host ----------------
extern "C" void kernel_launch(void* const* d_in, const int* in_sizes, int n_in,
                              void* d_out, int out_size) {
    const float* x_source = (const float*)d_in[0];
    const float* x_target = (const float*)d_in[1];
    const int* ei_st = (const int*)d_in[2];
    const int* ei_ts = (const int*)d_in[3];
    const float* Wl_st = (const float*)d_in[4];
    const float* Wr_st = (const float*)d_in[5];
    const float* b_st = (const float*)d_in[6];
    const float* Wl_ts = (const float*)d_in[7];
    const float* Wr_ts = (const float*)d_in[8];
    const float* b_ts = (const float*)d_in[9];
    const float* Wout = (const float*)d_in[10];
    const float* bout = (const float*)d_in[11];
    float* out = (float*)d_out;

    void* p;
    __half *pxs, *pxt, *pma, *pmb, *pxt0, *pxs0, *wfh;
    cudaGetSymbolAddress(&p, g_pxs);  pxs = (__half*)p;
    cudaGetSymbolAddress(&p, g_pxt);  pxt = (__half*)p;
    cudaGetSymbolAddress(&p, g_pma);  pma = (__half*)p;
    cudaGetSymbolAddress(&p, g_pmb);  pmb = (__half*)p;
    cudaGetSymbolAddress(&p, g_pxt0); pxt0 = (__half*)p;
    cudaGetSymbolAddress(&p, g_pxs0); pxs0 = (__half*)p;
    cudaGetSymbolAddress(&p, g_wfh);  wfh = (__half*)p;
    int *off_a, *off_b, *csr_a, *csr_b;
    cudaGetSymbolAddress(&p, g_off_a); off_a = (int*)p;
    cudaGetSymbolAddress(&p, g_off_b); off_b = (int*)p;
    cudaGetSymbolAddress(&p, g_csr_a); csr_a = (int*)p;
    cudaGetSymbolAddress(&p, g_csr_b); csr_b = (int*)p;

    cudaFuncSetAttribute(gemm_mma<false>, cudaFuncAttributeMaxDynamicSharedMemorySize, SMEM_GEMM);
    cudaFuncSetAttribute(gemm_mma<true>, cudaFuncAttributeMaxDynamicSharedMemorySize, SMEM_GEMM_F);

    const int* src_st = ei_st;
    const int* dst_st = ei_st + EE;
    const int* src_ts = ei_ts;
    const int* dst_ts = ei_ts + EE;

    // dropout keys: fold_in(key(42)=(0,42), d); d=0 -> xs0, d=1 -> xt0, d=2 -> xs1
    unsigned dkeys[3][2];
    for (int d = 0; d < 3; d++)
        tf2x32(0u, 42u, 0u, (unsigned)d, dkeys[d][0], dkeys[d][1]);

    wprep_kernel<<<dim3(256, 8), 256>>>(Wl_st, Wr_st, Wl_ts, Wr_ts);
    conv_kernel<<<dim3(12500, 2), 256>>>(x_source, x_target);
    init_kernel<<<(NN * 16 / 4 + 255) / 256, 256>>>(bout, out);
    count_kernel<<<(EE + 255) / 256, 256>>>(dst_st, dst_ts);
    scan_pre<<<dim3(49, 2), 256>>>();
    scan_mid<<<dim3(1, 2), 64>>>();
    scan_add<<<dim3(49, 2), 256>>>();
    fill_kernel<<<(EE + 255) / 256, 256>>>(src_st, dst_st, src_ts, dst_ts);

    const int M64K = 65536;
    const int segBlocks = (NN + 7) / 8;   // 6250

    // ---- layer 0: both segmeans in one launch, both gemms in one launch ----
    segmean2_kernel<<<dim3(segBlocks, 2), 256>>>(pxs, off_a, csr_a, pma,
                                                 pxt, off_b, csr_b, pmb);
    GArgs gA = {}, gB = {};
    // z=0: new_t = m_t@Wl_st + x_t@Wr_st + b_st -> pxt0 (key d=1)
    gA.A1 = pma; gA.A2 = pxt;
    gA.W1h = wfh + 0 * M64K; gA.W2h = wfh + 1 * M64K;
    gA.bias = b_st; gA.outC = pxt0; gA.dk0 = dkeys[1][0]; gA.dk1 = dkeys[1][1];
    // z=1: new_s = m_s@Wl_ts + x_s@Wr_ts + b_ts -> pxs0 (key d=0)
    gB.A1 = pmb; gB.A2 = pxs;
    gB.W1h = wfh + 2 * M64K; gB.W2h = wfh + 3 * M64K;
    gB.bias = b_ts; gB.outC = pxs0; gB.dk0 = dkeys[0][0]; gB.dk1 = dkeys[0][1];
    gemm_mma<false><<<dim3(2, NBLKY, 2), 256, SMEM_GEMM>>>(gA, gB, NN);

    // ---- layer 1 (target branch dead); projection fused into gemm epilogue ----
    segmean2_kernel<<<dim3(segBlocks, 1), 256>>>(pxt0, off_b, csr_b, pma,
                                                 pxt0, off_b, csr_b, pma);
    GArgs gC = {};
    gC.A1 = pma; gC.A2 = pxs0;
    gC.W1h = wfh + 6 * M64K; gC.W2h = wfh + 7 * M64K;
    gC.bias = b_ts + 256; gC.outC = nullptr;
    gC.Wproj = Wout; gC.outF = out;
    gC.dk0 = dkeys[2][0]; gC.dk1 = dkeys[2][1];
    gemm_mma<true><<<dim3(2, NBLKY, 1), 256, SMEM_GEMM_F>>>(gC, gC, NN);
}